// round 9
// baseline (speedup 1.0000x reference)
#include <cuda_runtime.h>
#include <math.h>
#include <stdint.h>

// Problem constants
static constexpr int Bb  = 8;
static constexpr int Tt  = 1024;
static constexpr int Uu  = 512;
static constexpr int DH  = 64;
static constexpr int HB  = 64;           // H*B
static constexpr int MR  = Bb * Tt;      // 8192 rows

// Scratch (device globals: allocation-free rule)
__device__ float g_qh[HB * Tt * DH];
__device__ float g_kh[HB * Tt * DH];
__device__ float g_vh[HB * Tt * DH];
__device__ float g_att[MR * Uu];

// ---------------------------------------------------------------------------
// Helpers
// ---------------------------------------------------------------------------
__device__ __forceinline__ uint32_t f2tf32(float f) {
    uint32_t u;
    asm("cvt.rna.tf32.f32 %0, %1;" : "=r"(u) : "f"(f));
    return u;
}

__device__ __forceinline__ void mma_tf32(float c[4], const uint32_t a[4], const uint32_t b[2]) {
    asm volatile(
        "mma.sync.aligned.m16n8k8.row.col.f32.tf32.tf32.f32 "
        "{%0,%1,%2,%3}, {%4,%5,%6,%7}, {%8,%9}, {%0,%1,%2,%3};"
        : "+f"(c[0]), "+f"(c[1]), "+f"(c[2]), "+f"(c[3])
        : "r"(a[0]), "r"(a[1]), "r"(a[2]), "r"(a[3]), "r"(b[0]), "r"(b[1]));
}

__device__ __forceinline__ void cp16(uint32_t saddr, const void* gptr) {
    asm volatile("cp.async.cg.shared.global [%0], [%1], 16;" :: "r"(saddr), "l"(gptr));
}

__device__ __forceinline__ uint32_t smem_u32(const void* p) {
    uint32_t a;
    asm("{ .reg .u64 t; cvta.to.shared.u64 t, %1; cvt.u32.u64 %0, t; }" : "=r"(a) : "l"(p));
    return a;
}

// ---------------------------------------------------------------------------
// QKV projection GEMM: 256x128 block tile, BK=16, 3-stage cp.async.
// 256 threads = 8 warps (4x2), warp tile 64x64.  z = blockIdx.z selects q/k/v.
// Output head-split with bias+relu.
// ---------------------------------------------------------------------------
struct ProjSmem {
    float As[3][256][20];   // 61440 B
    float Bs[3][16][136];   // 26112 B
};

__global__ __launch_bounds__(256) void proj_gemm(
    const float* __restrict__ q, const float* __restrict__ k, const float* __restrict__ v,
    const float* __restrict__ Wq, const float* __restrict__ Wk, const float* __restrict__ Wv,
    const float* __restrict__ bq, const float* __restrict__ bk, const float* __restrict__ bv)
{
    extern __shared__ __align__(1024) char smem_raw[];
    ProjSmem& sm = *reinterpret_cast<ProjSmem*>(smem_raw);

    const int z = blockIdx.z;
    const float* A    = (z == 0) ? q  : (z == 1) ? k  : v;
    const float* W    = (z == 0) ? Wq : (z == 1) ? Wk : Wv;
    const float* bias = (z == 0) ? bq : (z == 1) ? bk : bv;

    const int tid  = threadIdx.x;
    const int lane = tid & 31;
    const int wid  = tid >> 5;
    const int wm   = wid >> 1;            // 0..3
    const int wn   = wid & 1;             // 0..1
    const int kq   = lane & 3;
    const int ng   = lane >> 2;
    const int rowBase = blockIdx.y * 256;
    const int nBase   = blockIdx.x * 128;

    const uint32_t aS = smem_u32(&sm.As[0][0][0]);
    const uint32_t bS = smem_u32(&sm.Bs[0][0][0]);

    auto issue = [&](int s, int kt) {
        const int kb = kt * 16;
#pragma unroll
        for (int ii = 0; ii < 4; ++ii) {
            const int idx = tid + ii * 256;         // 0..1023
            const int r = idx >> 2, q4 = idx & 3;
            cp16(aS + (((s * 256 + r) * 20 + q4 * 4) << 2),
                 &A[(size_t)(rowBase + r) * Uu + kb + q4 * 4]);
        }
#pragma unroll
        for (int ii = 0; ii < 2; ++ii) {
            const int idx = tid + ii * 256;         // 0..511
            const int kr = idx >> 5, n4 = idx & 31;
            cp16(bS + (((s * 16 + kr) * 136 + n4 * 4) << 2),
                 &W[(size_t)(kb + kr) * Uu + nBase + n4 * 4]);
        }
        asm volatile("cp.async.commit_group;");
    };

    constexpr int NIT = Uu / 16;   // 32
    issue(0, 0);
    issue(1, 1);

    float c[4][8][4] = {};

    for (int kb = 0; kb < NIT; ++kb) {
        const int cur = kb % 3;
        if (kb + 1 < NIT) asm volatile("cp.async.wait_group 1;");
        else              asm volatile("cp.async.wait_group 0;");
        __syncthreads();

#pragma unroll
        for (int ks = 0; ks < 2; ++ks) {
            const int k0 = ks * 8 + kq;
            uint32_t a[4][4];
#pragma unroll
            for (int mt = 0; mt < 4; ++mt) {
                const int r0 = wm * 64 + mt * 16 + ng;
                a[mt][0] = f2tf32(sm.As[cur][r0][k0]);
                a[mt][1] = f2tf32(sm.As[cur][r0 + 8][k0]);
                a[mt][2] = f2tf32(sm.As[cur][r0][k0 + 4]);
                a[mt][3] = f2tf32(sm.As[cur][r0 + 8][k0 + 4]);
            }
#pragma unroll
            for (int nt = 0; nt < 8; ++nt) {
                uint32_t b[2];
                const int n0 = wn * 64 + nt * 8 + ng;
                b[0] = f2tf32(sm.Bs[cur][k0][n0]);
                b[1] = f2tf32(sm.Bs[cur][k0 + 4][n0]);
#pragma unroll
                for (int mt = 0; mt < 4; ++mt)
                    mma_tf32(c[mt][nt], a[mt], b);
            }
        }

        if (kb + 2 < NIT) issue((kb + 2) % 3, kb + 2);
    }

    // Epilogue: bias + relu, head-split scatter
    float* dst = (z == 0) ? g_qh : (z == 1) ? g_kh : g_vh;
#pragma unroll
    for (int mt = 0; mt < 4; ++mt) {
        const int rbase = rowBase + wm * 64 + mt * 16 + ng;
#pragma unroll
        for (int nt = 0; nt < 8; ++nt) {
            const int n = nBase + wn * 64 + nt * 8 + 2 * kq;
            const float2 bi = *(const float2*)&bias[n];
            const int h = n >> 6, d = n & 63;
#pragma unroll
            for (int half = 0; half < 2; ++half) {
                const int m = rbase + half * 8;
                const int bidx = m >> 10, t = m & 1023;
                float2 o;
                o.x = fmaxf(c[mt][nt][half * 2 + 0] + bi.x, 0.f);
                o.y = fmaxf(c[mt][nt][half * 2 + 1] + bi.y, 0.f);
                *(float2*)&dst[((size_t)(h * 8 + bidx) * Tt + t) * DH + d] = o;
            }
        }
    }
}

// ---------------------------------------------------------------------------
// Fused out-projection + residual + LayerNorm.
// One block = 64 full rows (tile 64x512).  256 threads = 8 warps; warp w owns
// cols [w*64, w*64+64).  3-stage cp.async on A (g_att) and B (Wo).
// Epilogue: relu(c+bo)+q residual, LN stats via quad-shfl + smem cross-warp
// reduction, normalized output written directly to d_out.
// ---------------------------------------------------------------------------
struct OProjSmem {
    float As[3][64][20];     // 15360 B
    float Bs[3][16][520];    // 99840 B
    float part[2][8][64];    // 4096 B  [sum/sq][warp][row]
    float mu[64];
    float rs[64];
};

__global__ __launch_bounds__(256) void oproj_ln(
    const float* __restrict__ Wo, const float* __restrict__ bo,
    const float* __restrict__ res,
    const float* __restrict__ gamma, const float* __restrict__ beta,
    float* __restrict__ out)
{
    extern __shared__ __align__(1024) char smem_raw[];
    OProjSmem& sm = *reinterpret_cast<OProjSmem*>(smem_raw);

    const int tid  = threadIdx.x;
    const int lane = tid & 31;
    const int w    = tid >> 5;
    const int kq   = lane & 3;
    const int ng   = lane >> 2;
    const int rowBase = blockIdx.x * 64;

    const uint32_t aS = smem_u32(&sm.As[0][0][0]);
    const uint32_t bS = smem_u32(&sm.Bs[0][0][0]);

    auto issue = [&](int s, int kt) {
        const int kb = kt * 16;
        {
            const int idx = tid;                 // 0..255
            const int r = idx >> 2, q4 = idx & 3;
            cp16(aS + (((s * 64 + r) * 20 + q4 * 4) << 2),
                 &g_att[(size_t)(rowBase + r) * Uu + kb + q4 * 4]);
        }
#pragma unroll
        for (int ii = 0; ii < 8; ++ii) {
            const int idx = tid + ii * 256;      // 0..2047
            const int kr = idx >> 7, n4 = idx & 127;
            cp16(bS + (((s * 16 + kr) * 520 + n4 * 4) << 2),
                 &Wo[(size_t)(kb + kr) * Uu + n4 * 4]);
        }
        asm volatile("cp.async.commit_group;");
    };

    constexpr int NIT = Uu / 16;   // 32
    issue(0, 0);
    issue(1, 1);

    float c[4][8][4] = {};

    for (int kb = 0; kb < NIT; ++kb) {
        const int cur = kb % 3;
        if (kb + 1 < NIT) asm volatile("cp.async.wait_group 1;");
        else              asm volatile("cp.async.wait_group 0;");
        __syncthreads();

#pragma unroll
        for (int ks = 0; ks < 2; ++ks) {
            const int k0 = ks * 8 + kq;
            uint32_t a[4][4];
#pragma unroll
            for (int mt = 0; mt < 4; ++mt) {
                const int r0 = mt * 16 + ng;
                a[mt][0] = f2tf32(sm.As[cur][r0][k0]);
                a[mt][1] = f2tf32(sm.As[cur][r0 + 8][k0]);
                a[mt][2] = f2tf32(sm.As[cur][r0][k0 + 4]);
                a[mt][3] = f2tf32(sm.As[cur][r0 + 8][k0 + 4]);
            }
#pragma unroll
            for (int nt = 0; nt < 8; ++nt) {
                uint32_t b[2];
                const int n0 = w * 64 + nt * 8 + ng;
                b[0] = f2tf32(sm.Bs[cur][k0][n0]);
                b[1] = f2tf32(sm.Bs[cur][k0 + 4][n0]);
#pragma unroll
                for (int mt = 0; mt < 4; ++mt)
                    mma_tf32(c[mt][nt], a[mt], b);
            }
        }

        if (kb + 2 < NIT) issue((kb + 2) % 3, kb + 2);
    }

    // ---- bias + relu + residual; accumulate per-row partial stats ----
    float psum[8] = {}, psq[8] = {};
#pragma unroll
    for (int mt = 0; mt < 4; ++mt) {
#pragma unroll
        for (int half = 0; half < 2; ++half) {
            const int m = rowBase + mt * 16 + ng + half * 8;
            const int slot = mt * 2 + half;
#pragma unroll
            for (int nt = 0; nt < 8; ++nt) {
                const int n = w * 64 + nt * 8 + 2 * kq;
                const float2 bi = *(const float2*)&bo[n];
                const float2 r2 = *(const float2*)&res[(size_t)m * Uu + n];
                float vx = fmaxf(c[mt][nt][half * 2 + 0] + bi.x, 0.f) + r2.x;
                float vy = fmaxf(c[mt][nt][half * 2 + 1] + bi.y, 0.f) + r2.y;
                c[mt][nt][half * 2 + 0] = vx;
                c[mt][nt][half * 2 + 1] = vy;
                psum[slot] += vx + vy;
                psq[slot]  += vx * vx + vy * vy;
            }
        }
    }
    // quad reduce (cols within warp)
#pragma unroll
    for (int slot = 0; slot < 8; ++slot) {
        psum[slot] += __shfl_xor_sync(0xffffffffu, psum[slot], 1);
        psum[slot] += __shfl_xor_sync(0xffffffffu, psum[slot], 2);
        psq[slot]  += __shfl_xor_sync(0xffffffffu, psq[slot], 1);
        psq[slot]  += __shfl_xor_sync(0xffffffffu, psq[slot], 2);
    }
    if (kq == 0) {
#pragma unroll
        for (int mt = 0; mt < 4; ++mt)
#pragma unroll
            for (int half = 0; half < 2; ++half) {
                const int rl = mt * 16 + ng + half * 8;
                sm.part[0][w][rl] = psum[mt * 2 + half];
                sm.part[1][w][rl] = psq[mt * 2 + half];
            }
    }
    __syncthreads();

    if (tid < 64) {
        float su = 0.f, sq = 0.f;
#pragma unroll
        for (int wi = 0; wi < 8; ++wi) {
            su += sm.part[0][wi][tid];
            sq += sm.part[1][wi][tid];
        }
        const float mu = su * (1.f / Uu);
        const float var = sq * (1.f / Uu) - mu * mu;
        sm.mu[tid] = mu;
        sm.rs[tid] = rsqrtf(var + 1e-3f);
    }
    __syncthreads();

    // ---- normalize + gamma/beta + write final output ----
#pragma unroll
    for (int mt = 0; mt < 4; ++mt) {
#pragma unroll
        for (int half = 0; half < 2; ++half) {
            const int rl = mt * 16 + ng + half * 8;
            const int m = rowBase + rl;
            const float mu = sm.mu[rl];
            const float rstd = sm.rs[rl];
#pragma unroll
            for (int nt = 0; nt < 8; ++nt) {
                const int n = w * 64 + nt * 8 + 2 * kq;
                const float2 g2 = *(const float2*)&gamma[n];
                const float2 b2 = *(const float2*)&beta[n];
                float2 o;
                o.x = (c[mt][nt][half * 2 + 0] - mu) * rstd * g2.x + b2.x;
                o.y = (c[mt][nt][half * 2 + 1] - mu) * rstd * g2.y + b2.y;
                *(float2*)&out[(size_t)m * Uu + n] = o;
            }
        }
    }
}

// ---------------------------------------------------------------------------
// Tensor-core flash attention (validated round-6/7 kernel, unchanged).
// ---------------------------------------------------------------------------
struct AttnSmem {
    uint32_t K[2][64][68];
    uint32_t V[2][64][72];
    union { uint32_t Q[64][68]; float pev[17][68]; };
    union { uint32_t P[64][68]; float pek[17][68]; };
    float qrel[64][17];
    float wsum[64][16];
};

__global__ __launch_bounds__(128) void attn_kernel(
    const float* __restrict__ pe_k, const float* __restrict__ pe_v)
{
    extern __shared__ __align__(16) char smem_raw[];
    AttnSmem& s = *reinterpret_cast<AttnSmem*>(smem_raw);

    const int tid  = threadIdx.x;
    const int lane = tid & 31;
    const int w    = tid >> 5;
    const int kq   = lane & 3;
    const int ng   = lane >> 2;
    const int it   = 15 - (int)blockIdx.x;
    const int hb   = blockIdx.y;
    const int h = hb >> 3, bidx = hb & 7;

    const float* qbase = g_qh + (size_t)hb * Tt * DH;
    const float* kbase = g_kh + (size_t)hb * Tt * DH;
    const float* vbase = g_vh + (size_t)hb * Tt * DH;

    const uint32_t kS = smem_u32(&s.K[0][0][0]);
    const uint32_t vS = smem_u32(&s.V[0][0][0]);

    auto issue_tile = [&](int buf, int jt) {
#pragma unroll
        for (int ii = 0; ii < 8; ++ii) {
            const int i = tid + ii * 128;
            const int c = i >> 4, dq = i & 15;
            cp16(kS + (((buf * 64 + c) * 68 + dq * 4) << 2),
                 &kbase[(size_t)(jt * 64 + c) * DH + dq * 4]);
            cp16(vS + (((buf * 64 + c) * 72 + dq * 4) << 2),
                 &vbase[(size_t)(jt * 64 + c) * DH + dq * 4]);
        }
        asm volatile("cp.async.commit_group;");
    };

    issue_tile(0, 0);

    for (int i = tid; i < 1024; i += 128) {
        int r = i >> 4, dq = i & 15;
        float4 a = *(const float4*)&qbase[(size_t)(it * 64 + r) * DH + dq * 4];
        s.Q[r][dq * 4 + 0] = f2tf32(a.x * 0.125f);
        s.Q[r][dq * 4 + 1] = f2tf32(a.y * 0.125f);
        s.Q[r][dq * 4 + 2] = f2tf32(a.z * 0.125f);
        s.Q[r][dq * 4 + 3] = f2tf32(a.w * 0.125f);
    }
    for (int i = tid; i < 17 * 16; i += 128) {
        int m = i / 16, dq = i % 16;
        *(float4*)&s.pek[m][dq * 4] = *(const float4*)&pe_k[m * DH + dq * 4];
    }
    for (int i = tid; i < 1024; i += 128)
        (&s.wsum[0][0])[i] = 0.f;
    __syncthreads();

    for (int i = tid; i < 64 * 17; i += 128) {
        int r = i / 17, m = i % 17;
        float acc = 0.f;
#pragma unroll 16
        for (int d = 0; d < DH; ++d)
            acc = fmaf(__uint_as_float(s.Q[r][d]), s.pek[m][d], acc);
        s.qrel[r][m] = acc;
    }
    __syncthreads();

    const int rl0 = w * 16 + ng;
    const float qrel0_0 = s.qrel[rl0][0];
    const float qrel0_1 = s.qrel[rl0 + 8][0];

    float o[8][4] = {};
    float mrow[2] = {-1e30f, -1e30f};
    float lrow[2] = {};

    for (int jt = 0; jt <= it; ++jt) {
        const int cur = jt & 1;
        if (jt < it) {
            issue_tile(cur ^ 1, jt + 1);
            asm volatile("cp.async.wait_group 1;");
        } else {
            asm volatile("cp.async.wait_group 0;");
        }
        __syncthreads();

        float sc[8][4] = {};
#pragma unroll
        for (int ks = 0; ks < 8; ++ks) {
            const int k0 = ks * 8 + kq;
            uint32_t a[4];
            a[0] = s.Q[rl0][k0];
            a[1] = s.Q[rl0 + 8][k0];
            a[2] = s.Q[rl0][k0 + 4];
            a[3] = s.Q[rl0 + 8][k0 + 4];
#pragma unroll
            for (int nt = 0; nt < 8; ++nt) {
                uint32_t b[2];
                b[0] = s.K[cur][nt * 8 + ng][k0];
                b[1] = s.K[cur][nt * 8 + ng][k0 + 4];
                mma_tf32(sc[nt], a, b);
            }
        }

        const bool near = (jt >= it - 1);
        if (near) {
#pragma unroll
            for (int nt = 0; nt < 8; ++nt) {
#pragma unroll
                for (int ci = 0; ci < 4; ++ci) {
                    const int row_l = rl0 + ((ci >> 1) << 3);
                    const int tg = it * 64 + row_l;
                    const int sg = jt * 64 + nt * 8 + 2 * kq + (ci & 1);
                    const int delta = sg - tg;
                    if (delta > 0) sc[nt][ci] = -1e30f;
                    else {
                        int mi = delta + 16; if (mi < 0) mi = 0;
                        sc[nt][ci] += s.qrel[row_l][mi];
                    }
                }
            }
        } else {
#pragma unroll
            for (int nt = 0; nt < 8; ++nt) {
                sc[nt][0] += qrel0_0;
                sc[nt][1] += qrel0_0;
                sc[nt][2] += qrel0_1;
                sc[nt][3] += qrel0_1;
            }
        }

        float mt0 = -1e30f, mt1 = -1e30f;
#pragma unroll
        for (int nt = 0; nt < 8; ++nt) {
            mt0 = fmaxf(mt0, fmaxf(sc[nt][0], sc[nt][1]));
            mt1 = fmaxf(mt1, fmaxf(sc[nt][2], sc[nt][3]));
        }
        mt0 = fmaxf(mt0, __shfl_xor_sync(0xffffffffu, mt0, 1));
        mt0 = fmaxf(mt0, __shfl_xor_sync(0xffffffffu, mt0, 2));
        mt1 = fmaxf(mt1, __shfl_xor_sync(0xffffffffu, mt1, 1));
        mt1 = fmaxf(mt1, __shfl_xor_sync(0xffffffffu, mt1, 2));

        const float mnew0 = fmaxf(mrow[0], mt0);
        const float mnew1 = fmaxf(mrow[1], mt1);
        const float alpha0 = __expf(mrow[0] - mnew0);
        const float alpha1 = __expf(mrow[1] - mnew1);
        mrow[0] = mnew0; mrow[1] = mnew1;

        float ps0 = 0.f, ps1 = 0.f;
#pragma unroll
        for (int nt = 0; nt < 8; ++nt) {
            sc[nt][0] = __expf(sc[nt][0] - mnew0);
            sc[nt][1] = __expf(sc[nt][1] - mnew0);
            sc[nt][2] = __expf(sc[nt][2] - mnew1);
            sc[nt][3] = __expf(sc[nt][3] - mnew1);
            ps0 += sc[nt][0] + sc[nt][1];
            ps1 += sc[nt][2] + sc[nt][3];
        }
        ps0 += __shfl_xor_sync(0xffffffffu, ps0, 1);
        ps0 += __shfl_xor_sync(0xffffffffu, ps0, 2);
        ps1 += __shfl_xor_sync(0xffffffffu, ps1, 1);
        ps1 += __shfl_xor_sync(0xffffffffu, ps1, 2);
        lrow[0] = lrow[0] * alpha0 + ps0;
        lrow[1] = lrow[1] * alpha1 + ps1;

#pragma unroll
        for (int nt = 0; nt < 8; ++nt) {
            o[nt][0] *= alpha0; o[nt][1] *= alpha0;
            o[nt][2] *= alpha1; o[nt][3] *= alpha1;
        }

#pragma unroll
        for (int j = 0; j < 4; ++j) {
            s.wsum[rl0][kq * 4 + j]     *= alpha0;
            s.wsum[rl0 + 8][kq * 4 + j] *= alpha1;
        }
        __syncwarp();
        if (near) {
#pragma unroll
            for (int nt = 0; nt < 8; ++nt) {
#pragma unroll
                for (int ci = 0; ci < 4; ++ci) {
                    const int row_l = rl0 + ((ci >> 1) << 3);
                    const int delta = (jt * 64 + nt * 8 + 2 * kq + (ci & 1)) - (it * 64 + row_l);
                    if (delta >= -15 && delta <= 0)
                        s.wsum[row_l][delta + 15] += sc[nt][ci];
                }
            }
        }
        __syncwarp();

#pragma unroll
        for (int nt = 0; nt < 8; ++nt) {
            const int c0 = nt * 8 + 2 * kq;
            s.P[rl0][c0]         = __float_as_uint(sc[nt][0]);
            s.P[rl0][c0 + 1]     = __float_as_uint(sc[nt][1]);
            s.P[rl0 + 8][c0]     = __float_as_uint(sc[nt][2]);
            s.P[rl0 + 8][c0 + 1] = __float_as_uint(sc[nt][3]);
        }
        __syncwarp();

#pragma unroll
        for (int ks = 0; ks < 8; ++ks) {
            const int k0 = ks * 8 + kq;
            uint32_t a[4];
            a[0] = s.P[rl0][k0];
            a[1] = s.P[rl0 + 8][k0];
            a[2] = s.P[rl0][k0 + 4];
            a[3] = s.P[rl0 + 8][k0 + 4];
#pragma unroll
            for (int nt = 0; nt < 8; ++nt) {
                uint32_t b[2];
                b[0] = s.V[cur][k0][nt * 8 + ng];
                b[1] = s.V[cur][k0 + 4][nt * 8 + ng];
                mma_tf32(o[nt], a, b);
            }
        }
        __syncthreads();
    }

    for (int i = tid; i < 17 * 16; i += 128) {
        int m = i / 16, dq = i % 16;
        *(float4*)&s.pev[m][dq * 4] = *(const float4*)&pe_v[m * DH + dq * 4];
    }
    __syncthreads();

#pragma unroll
    for (int half = 0; half < 2; ++half) {
        const int rl = rl0 + 8 * half;
        const int tg = it * 64 + rl;
        const float l = lrow[half];
        float wm[16], sumw = 0.f;
#pragma unroll
        for (int m = 0; m < 16; ++m) { wm[m] = s.wsum[rl][m]; sumw += wm[m]; }
        const float w0 = l - sumw;
        const float inv = 1.f / l;
#pragma unroll
        for (int nt = 0; nt < 8; ++nt) {
            const int d0 = nt * 8 + 2 * kq;
            float acc0 = o[nt][half * 2 + 0] + w0 * s.pev[0][d0];
            float acc1 = o[nt][half * 2 + 1] + w0 * s.pev[0][d0 + 1];
#pragma unroll
            for (int m = 1; m <= 16; ++m) {
                acc0 = fmaf(wm[m - 1], s.pev[m][d0], acc0);
                acc1 = fmaf(wm[m - 1], s.pev[m][d0 + 1], acc1);
            }
            float2 ov = make_float2(acc0 * inv, acc1 * inv);
            *(float2*)&g_att[((size_t)(bidx * Tt) + tg) * Uu + h * DH + d0] = ov;
        }
    }
}

// ---------------------------------------------------------------------------
extern "C" void kernel_launch(void* const* d_in, const int* in_sizes, int n_in,
                              void* d_out, int out_size) {
    (void)n_in; (void)out_size;

    int iq, ik, iv, iWq, ibq, iWk, ibk, iWv, ibv, iWo, ibo, ig, ibe, ipk, ipv;
    if (in_sizes[0] == Bb * Tt * Uu) {
        iq = 0; ik = 1; iv = 2; iWq = 3; ibq = 4; iWk = 5; ibk = 6;
        iWv = 7; ibv = 8; iWo = 9; ibo = 10; ig = 11; ibe = 12; ipk = 13; ipv = 14;
    } else if (in_sizes[0] == Uu * Uu) {
        iWk = 0; iWo = 1; iWq = 2; iWv = 3; ibe = 4; ibk = 5; ibo = 6;
        ibq = 7; ibv = 8; ig = 9; ik = 10; ipk = 11; ipv = 12; iq = 13; iv = 14;
    } else {
        ibe = 0; ibk = 1; ibo = 2; ibq = 3; ibv = 4; ig = 5; ik = 6;
        ipk = 7; ipv = 8; iq = 9; iv = 10; iWk = 11; iWo = 12; iWq = 13; iWv = 14;
    }

    const float* q    = (const float*)d_in[iq];
    const float* k    = (const float*)d_in[ik];
    const float* v    = (const float*)d_in[iv];
    const float* Wq   = (const float*)d_in[iWq];
    const float* bq   = (const float*)d_in[ibq];
    const float* Wk   = (const float*)d_in[iWk];
    const float* bk   = (const float*)d_in[ibk];
    const float* Wv   = (const float*)d_in[iWv];
    const float* bv   = (const float*)d_in[ibv];
    const float* Wo   = (const float*)d_in[iWo];
    const float* bo   = (const float*)d_in[ibo];
    const float* gamma= (const float*)d_in[ig];
    const float* beta = (const float*)d_in[ibe];
    const float* pek  = (const float*)d_in[ipk];
    const float* pev  = (const float*)d_in[ipv];
    float* out = (float*)d_out;

    cudaFuncSetAttribute(attn_kernel, cudaFuncAttributeMaxDynamicSharedMemorySize,
                         (int)sizeof(AttnSmem));
    cudaFuncSetAttribute(proj_gemm, cudaFuncAttributeMaxDynamicSharedMemorySize,
                         (int)sizeof(ProjSmem));
    cudaFuncSetAttribute(oproj_ln, cudaFuncAttributeMaxDynamicSharedMemorySize,
                         (int)sizeof(OProjSmem));

    // Q/K/V projections (one launch, z = 0/1/2)
    proj_gemm<<<dim3(4, 32, 3), 256, sizeof(ProjSmem)>>>(
        q, k, v, Wq, Wk, Wv, bq, bk, bv);

    attn_kernel<<<dim3(16, 64), 128, sizeof(AttnSmem)>>>(pek, pev);

    // Fused output projection + residual + LayerNorm -> final output
    oproj_ln<<<128, 256, sizeof(OProjSmem)>>>(Wo, bo, q, gamma, beta, out);
}

// round 10
// speedup vs baseline: 1.0210x; 1.0210x over previous
#include <cuda_runtime.h>
#include <math.h>
#include <stdint.h>

// Problem constants
static constexpr int Bb  = 8;
static constexpr int Tt  = 1024;
static constexpr int Uu  = 512;
static constexpr int DH  = 64;
static constexpr int HB  = 64;           // H*B
static constexpr int MR  = Bb * Tt;      // 8192 rows

// Scratch (device globals: allocation-free rule)
__device__ float g_qh[HB * Tt * DH];
__device__ float g_kh[HB * Tt * DH];
__device__ float g_vh[HB * Tt * DH];
__device__ float g_att[MR * Uu];

// ---------------------------------------------------------------------------
// Helpers
// ---------------------------------------------------------------------------
__device__ __forceinline__ uint32_t f2tf32(float f) {
    uint32_t u;
    asm("cvt.rna.tf32.f32 %0, %1;" : "=r"(u) : "f"(f));
    return u;
}

__device__ __forceinline__ void mma_tf32(float c[4], const uint32_t a[4], const uint32_t b[2]) {
    asm volatile(
        "mma.sync.aligned.m16n8k8.row.col.f32.tf32.tf32.f32 "
        "{%0,%1,%2,%3}, {%4,%5,%6,%7}, {%8,%9}, {%0,%1,%2,%3};"
        : "+f"(c[0]), "+f"(c[1]), "+f"(c[2]), "+f"(c[3])
        : "r"(a[0]), "r"(a[1]), "r"(a[2]), "r"(a[3]), "r"(b[0]), "r"(b[1]));
}

__device__ __forceinline__ void cp16(uint32_t saddr, const void* gptr) {
    asm volatile("cp.async.cg.shared.global [%0], [%1], 16;" :: "r"(saddr), "l"(gptr));
}

__device__ __forceinline__ uint32_t smem_u32(const void* p) {
    uint32_t a;
    asm("{ .reg .u64 t; cvta.to.shared.u64 t, %1; cvt.u32.u64 %0, t; }" : "=r"(a) : "l"(p));
    return a;
}

// ---------------------------------------------------------------------------
// QKV projection GEMM: 128x128 tile, BK=32, 3-stage cp.async, 256 threads
// (8 warps 2x4, warp tile 64x32), 2 CTAs/SM (smem 107.5KB, regs capped 128).
// z = blockIdx.z selects q/k/v.  Output head-split with bias+relu.
// ---------------------------------------------------------------------------
struct ProjSmem {
    float As[3][128][36];   // 55296 B ; a-frag banks: 4*ng + kq -> conflict-free
    float Bs[3][32][136];   // 52224 B ; b-frag banks: 8*kq + ng -> conflict-free
};

__global__ __launch_bounds__(256, 2) void proj_gemm(
    const float* __restrict__ q, const float* __restrict__ k, const float* __restrict__ v,
    const float* __restrict__ Wq, const float* __restrict__ Wk, const float* __restrict__ Wv,
    const float* __restrict__ bq, const float* __restrict__ bk, const float* __restrict__ bv)
{
    extern __shared__ __align__(1024) char smem_raw[];
    ProjSmem& sm = *reinterpret_cast<ProjSmem*>(smem_raw);

    const int z = blockIdx.z;
    const float* A    = (z == 0) ? q  : (z == 1) ? k  : v;
    const float* W    = (z == 0) ? Wq : (z == 1) ? Wk : Wv;
    const float* bias = (z == 0) ? bq : (z == 1) ? bk : bv;

    const int tid  = threadIdx.x;
    const int lane = tid & 31;
    const int wid  = tid >> 5;
    const int wm   = wid >> 2;            // 0..1
    const int wn   = wid & 3;             // 0..3
    const int kq   = lane & 3;
    const int ng   = lane >> 2;
    const int rowBase = blockIdx.y * 128;
    const int nBase   = blockIdx.x * 128;

    const uint32_t aS = smem_u32(&sm.As[0][0][0]);
    const uint32_t bS = smem_u32(&sm.Bs[0][0][0]);

    auto issue = [&](int s, int kt) {
        const int kb = kt * 32;
#pragma unroll
        for (int ii = 0; ii < 4; ++ii) {
            const int idx = tid + ii * 256;       // 0..1023 : A 128 rows x 8 quads
            const int r = idx >> 3, q4 = idx & 7;
            cp16(aS + (((s * 128 + r) * 36 + q4 * 4) << 2),
                 &A[(size_t)(rowBase + r) * Uu + kb + q4 * 4]);
        }
#pragma unroll
        for (int ii = 0; ii < 4; ++ii) {
            const int idx = tid + ii * 256;       // 0..1023 : B 32 krows x 32 quads
            const int kr = idx >> 5, n4 = idx & 31;
            cp16(bS + (((s * 32 + kr) * 136 + n4 * 4) << 2),
                 &W[(size_t)(kb + kr) * Uu + nBase + n4 * 4]);
        }
        asm volatile("cp.async.commit_group;");
    };

    constexpr int NIT = Uu / 32;   // 16
    issue(0, 0);
    issue(1, 1);

    const int r0 = wm * 64 + ng;
    const int n0 = wn * 32 + ng;

    float c[4][4][4] = {};

    for (int kb = 0; kb < NIT; ++kb) {
        const int cur = kb % 3;
        if (kb + 1 < NIT) asm volatile("cp.async.wait_group 1;");
        else              asm volatile("cp.async.wait_group 0;");
        __syncthreads();

#pragma unroll
        for (int ks = 0; ks < 4; ++ks) {
            const int k0 = ks * 8 + kq;
            uint32_t a[4][4];
#pragma unroll
            for (int mt = 0; mt < 4; ++mt) {
                const int rr = r0 + mt * 16;
                a[mt][0] = f2tf32(sm.As[cur][rr][k0]);
                a[mt][1] = f2tf32(sm.As[cur][rr + 8][k0]);
                a[mt][2] = f2tf32(sm.As[cur][rr][k0 + 4]);
                a[mt][3] = f2tf32(sm.As[cur][rr + 8][k0 + 4]);
            }
#pragma unroll
            for (int nt = 0; nt < 4; ++nt) {
                uint32_t b[2];
                b[0] = f2tf32(sm.Bs[cur][k0][n0 + nt * 8]);
                b[1] = f2tf32(sm.Bs[cur][k0 + 4][n0 + nt * 8]);
#pragma unroll
                for (int mt = 0; mt < 4; ++mt)
                    mma_tf32(c[mt][nt], a[mt], b);
            }
        }

        if (kb + 2 < NIT) issue((kb + 2) % 3, kb + 2);
    }

    // Epilogue: bias + relu, head-split scatter
    float* dst = (z == 0) ? g_qh : (z == 1) ? g_kh : g_vh;
#pragma unroll
    for (int mt = 0; mt < 4; ++mt) {
        const int rbase = rowBase + wm * 64 + mt * 16 + ng;
#pragma unroll
        for (int nt = 0; nt < 4; ++nt) {
            const int n = nBase + wn * 32 + nt * 8 + 2 * kq;
            const float2 bi = *(const float2*)&bias[n];
            const int h = n >> 6, d = n & 63;
#pragma unroll
            for (int half = 0; half < 2; ++half) {
                const int m = rbase + half * 8;
                const int bidx = m >> 10, t = m & 1023;
                float2 o;
                o.x = fmaxf(c[mt][nt][half * 2 + 0] + bi.x, 0.f);
                o.y = fmaxf(c[mt][nt][half * 2 + 1] + bi.y, 0.f);
                *(float2*)&dst[((size_t)(h * 8 + bidx) * Tt + t) * DH + d] = o;
            }
        }
    }
}

// ---------------------------------------------------------------------------
// Fused out-projection + residual + LayerNorm, 4-stage cp.async.
// One block = 64 full rows (tile 64x512).  256 threads = 8 warps; warp w owns
// cols [w*64, w*64+64).  Grid 128 (single wave) -> latency-oriented pipeline.
// ---------------------------------------------------------------------------
struct OProjSmem {
    float As[4][64][20];     // 20480 B
    float Bs[4][16][520];    // 133120 B
    float part[2][8][64];    // 4096 B
    float mu[64];
    float rs[64];
};

__global__ __launch_bounds__(256) void oproj_ln(
    const float* __restrict__ Wo, const float* __restrict__ bo,
    const float* __restrict__ res,
    const float* __restrict__ gamma, const float* __restrict__ beta,
    float* __restrict__ out)
{
    extern __shared__ __align__(1024) char smem_raw[];
    OProjSmem& sm = *reinterpret_cast<OProjSmem*>(smem_raw);

    const int tid  = threadIdx.x;
    const int lane = tid & 31;
    const int w    = tid >> 5;
    const int kq   = lane & 3;
    const int ng   = lane >> 2;
    const int rowBase = blockIdx.x * 64;

    const uint32_t aS = smem_u32(&sm.As[0][0][0]);
    const uint32_t bS = smem_u32(&sm.Bs[0][0][0]);

    auto issue = [&](int s, int kt) {
        const int kb = kt * 16;
        {
            const int r = tid >> 2, q4 = tid & 3;
            cp16(aS + (((s * 64 + r) * 20 + q4 * 4) << 2),
                 &g_att[(size_t)(rowBase + r) * Uu + kb + q4 * 4]);
        }
#pragma unroll
        for (int ii = 0; ii < 8; ++ii) {
            const int idx = tid + ii * 256;
            const int kr = idx >> 7, n4 = idx & 127;
            cp16(bS + (((s * 16 + kr) * 520 + n4 * 4) << 2),
                 &Wo[(size_t)(kb + kr) * Uu + n4 * 4]);
        }
        asm volatile("cp.async.commit_group;");
    };

    constexpr int NIT = Uu / 16;   // 32
    issue(0, 0);
    issue(1, 1);
    issue(2, 2);

    float c[4][8][4] = {};

    for (int kb = 0; kb < NIT; ++kb) {
        const int cur = kb & 3;
        if      (kb + 2 < NIT) asm volatile("cp.async.wait_group 2;");
        else if (kb + 1 < NIT) asm volatile("cp.async.wait_group 1;");
        else                   asm volatile("cp.async.wait_group 0;");
        __syncthreads();

#pragma unroll
        for (int ks = 0; ks < 2; ++ks) {
            const int k0 = ks * 8 + kq;
            uint32_t a[4][4];
#pragma unroll
            for (int mt = 0; mt < 4; ++mt) {
                const int r0 = mt * 16 + ng;
                a[mt][0] = f2tf32(sm.As[cur][r0][k0]);
                a[mt][1] = f2tf32(sm.As[cur][r0 + 8][k0]);
                a[mt][2] = f2tf32(sm.As[cur][r0][k0 + 4]);
                a[mt][3] = f2tf32(sm.As[cur][r0 + 8][k0 + 4]);
            }
#pragma unroll
            for (int nt = 0; nt < 8; ++nt) {
                uint32_t b[2];
                const int n0 = w * 64 + nt * 8 + ng;
                b[0] = f2tf32(sm.Bs[cur][k0][n0]);
                b[1] = f2tf32(sm.Bs[cur][k0 + 4][n0]);
#pragma unroll
                for (int mt = 0; mt < 4; ++mt)
                    mma_tf32(c[mt][nt], a[mt], b);
            }
        }

        if (kb + 3 < NIT) issue((kb + 3) & 3, kb + 3);
    }

    // ---- bias + relu + residual; accumulate per-row partial stats ----
    float psum[8] = {}, psq[8] = {};
#pragma unroll
    for (int mt = 0; mt < 4; ++mt) {
#pragma unroll
        for (int half = 0; half < 2; ++half) {
            const int m = rowBase + mt * 16 + ng + half * 8;
            const int slot = mt * 2 + half;
#pragma unroll
            for (int nt = 0; nt < 8; ++nt) {
                const int n = w * 64 + nt * 8 + 2 * kq;
                const float2 bi = *(const float2*)&bo[n];
                const float2 r2 = *(const float2*)&res[(size_t)m * Uu + n];
                float vx = fmaxf(c[mt][nt][half * 2 + 0] + bi.x, 0.f) + r2.x;
                float vy = fmaxf(c[mt][nt][half * 2 + 1] + bi.y, 0.f) + r2.y;
                c[mt][nt][half * 2 + 0] = vx;
                c[mt][nt][half * 2 + 1] = vy;
                psum[slot] += vx + vy;
                psq[slot]  += vx * vx + vy * vy;
            }
        }
    }
#pragma unroll
    for (int slot = 0; slot < 8; ++slot) {
        psum[slot] += __shfl_xor_sync(0xffffffffu, psum[slot], 1);
        psum[slot] += __shfl_xor_sync(0xffffffffu, psum[slot], 2);
        psq[slot]  += __shfl_xor_sync(0xffffffffu, psq[slot], 1);
        psq[slot]  += __shfl_xor_sync(0xffffffffu, psq[slot], 2);
    }
    if (kq == 0) {
#pragma unroll
        for (int mt = 0; mt < 4; ++mt)
#pragma unroll
            for (int half = 0; half < 2; ++half) {
                const int rl = mt * 16 + ng + half * 8;
                sm.part[0][w][rl] = psum[mt * 2 + half];
                sm.part[1][w][rl] = psq[mt * 2 + half];
            }
    }
    __syncthreads();

    if (tid < 64) {
        float su = 0.f, sq = 0.f;
#pragma unroll
        for (int wi = 0; wi < 8; ++wi) {
            su += sm.part[0][wi][tid];
            sq += sm.part[1][wi][tid];
        }
        const float mu = su * (1.f / Uu);
        const float var = sq * (1.f / Uu) - mu * mu;
        sm.mu[tid] = mu;
        sm.rs[tid] = rsqrtf(var + 1e-3f);
    }
    __syncthreads();

#pragma unroll
    for (int mt = 0; mt < 4; ++mt) {
#pragma unroll
        for (int half = 0; half < 2; ++half) {
            const int rl = mt * 16 + ng + half * 8;
            const int m = rowBase + rl;
            const float mu = sm.mu[rl];
            const float rstd = sm.rs[rl];
#pragma unroll
            for (int nt = 0; nt < 8; ++nt) {
                const int n = w * 64 + nt * 8 + 2 * kq;
                const float2 g2 = *(const float2*)&gamma[n];
                const float2 b2 = *(const float2*)&beta[n];
                float2 o;
                o.x = (c[mt][nt][half * 2 + 0] - mu) * rstd * g2.x + b2.x;
                o.y = (c[mt][nt][half * 2 + 1] - mu) * rstd * g2.y + b2.y;
                *(float2*)&out[(size_t)m * Uu + n] = o;
            }
        }
    }
}

// ---------------------------------------------------------------------------
// Tensor-core flash attention (validated round-6/7 kernel, unchanged).
// ---------------------------------------------------------------------------
struct AttnSmem {
    uint32_t K[2][64][68];
    uint32_t V[2][64][72];
    union { uint32_t Q[64][68]; float pev[17][68]; };
    union { uint32_t P[64][68]; float pek[17][68]; };
    float qrel[64][17];
    float wsum[64][16];
};

__global__ __launch_bounds__(128) void attn_kernel(
    const float* __restrict__ pe_k, const float* __restrict__ pe_v)
{
    extern __shared__ __align__(16) char smem_raw[];
    AttnSmem& s = *reinterpret_cast<AttnSmem*>(smem_raw);

    const int tid  = threadIdx.x;
    const int lane = tid & 31;
    const int w    = tid >> 5;
    const int kq   = lane & 3;
    const int ng   = lane >> 2;
    const int it   = 15 - (int)blockIdx.x;
    const int hb   = blockIdx.y;
    const int h = hb >> 3, bidx = hb & 7;

    const float* qbase = g_qh + (size_t)hb * Tt * DH;
    const float* kbase = g_kh + (size_t)hb * Tt * DH;
    const float* vbase = g_vh + (size_t)hb * Tt * DH;

    const uint32_t kS = smem_u32(&s.K[0][0][0]);
    const uint32_t vS = smem_u32(&s.V[0][0][0]);

    auto issue_tile = [&](int buf, int jt) {
#pragma unroll
        for (int ii = 0; ii < 8; ++ii) {
            const int i = tid + ii * 128;
            const int c = i >> 4, dq = i & 15;
            cp16(kS + (((buf * 64 + c) * 68 + dq * 4) << 2),
                 &kbase[(size_t)(jt * 64 + c) * DH + dq * 4]);
            cp16(vS + (((buf * 64 + c) * 72 + dq * 4) << 2),
                 &vbase[(size_t)(jt * 64 + c) * DH + dq * 4]);
        }
        asm volatile("cp.async.commit_group;");
    };

    issue_tile(0, 0);

    for (int i = tid; i < 1024; i += 128) {
        int r = i >> 4, dq = i & 15;
        float4 a = *(const float4*)&qbase[(size_t)(it * 64 + r) * DH + dq * 4];
        s.Q[r][dq * 4 + 0] = f2tf32(a.x * 0.125f);
        s.Q[r][dq * 4 + 1] = f2tf32(a.y * 0.125f);
        s.Q[r][dq * 4 + 2] = f2tf32(a.z * 0.125f);
        s.Q[r][dq * 4 + 3] = f2tf32(a.w * 0.125f);
    }
    for (int i = tid; i < 17 * 16; i += 128) {
        int m = i / 16, dq = i % 16;
        *(float4*)&s.pek[m][dq * 4] = *(const float4*)&pe_k[m * DH + dq * 4];
    }
    for (int i = tid; i < 1024; i += 128)
        (&s.wsum[0][0])[i] = 0.f;
    __syncthreads();

    for (int i = tid; i < 64 * 17; i += 128) {
        int r = i / 17, m = i % 17;
        float acc = 0.f;
#pragma unroll 16
        for (int d = 0; d < DH; ++d)
            acc = fmaf(__uint_as_float(s.Q[r][d]), s.pek[m][d], acc);
        s.qrel[r][m] = acc;
    }
    __syncthreads();

    const int rl0 = w * 16 + ng;
    const float qrel0_0 = s.qrel[rl0][0];
    const float qrel0_1 = s.qrel[rl0 + 8][0];

    float o[8][4] = {};
    float mrow[2] = {-1e30f, -1e30f};
    float lrow[2] = {};

    for (int jt = 0; jt <= it; ++jt) {
        const int cur = jt & 1;
        if (jt < it) {
            issue_tile(cur ^ 1, jt + 1);
            asm volatile("cp.async.wait_group 1;");
        } else {
            asm volatile("cp.async.wait_group 0;");
        }
        __syncthreads();

        float sc[8][4] = {};
#pragma unroll
        for (int ks = 0; ks < 8; ++ks) {
            const int k0 = ks * 8 + kq;
            uint32_t a[4];
            a[0] = s.Q[rl0][k0];
            a[1] = s.Q[rl0 + 8][k0];
            a[2] = s.Q[rl0][k0 + 4];
            a[3] = s.Q[rl0 + 8][k0 + 4];
#pragma unroll
            for (int nt = 0; nt < 8; ++nt) {
                uint32_t b[2];
                b[0] = s.K[cur][nt * 8 + ng][k0];
                b[1] = s.K[cur][nt * 8 + ng][k0 + 4];
                mma_tf32(sc[nt], a, b);
            }
        }

        const bool near = (jt >= it - 1);
        if (near) {
#pragma unroll
            for (int nt = 0; nt < 8; ++nt) {
#pragma unroll
                for (int ci = 0; ci < 4; ++ci) {
                    const int row_l = rl0 + ((ci >> 1) << 3);
                    const int tg = it * 64 + row_l;
                    const int sg = jt * 64 + nt * 8 + 2 * kq + (ci & 1);
                    const int delta = sg - tg;
                    if (delta > 0) sc[nt][ci] = -1e30f;
                    else {
                        int mi = delta + 16; if (mi < 0) mi = 0;
                        sc[nt][ci] += s.qrel[row_l][mi];
                    }
                }
            }
        } else {
#pragma unroll
            for (int nt = 0; nt < 8; ++nt) {
                sc[nt][0] += qrel0_0;
                sc[nt][1] += qrel0_0;
                sc[nt][2] += qrel0_1;
                sc[nt][3] += qrel0_1;
            }
        }

        float mt0 = -1e30f, mt1 = -1e30f;
#pragma unroll
        for (int nt = 0; nt < 8; ++nt) {
            mt0 = fmaxf(mt0, fmaxf(sc[nt][0], sc[nt][1]));
            mt1 = fmaxf(mt1, fmaxf(sc[nt][2], sc[nt][3]));
        }
        mt0 = fmaxf(mt0, __shfl_xor_sync(0xffffffffu, mt0, 1));
        mt0 = fmaxf(mt0, __shfl_xor_sync(0xffffffffu, mt0, 2));
        mt1 = fmaxf(mt1, __shfl_xor_sync(0xffffffffu, mt1, 1));
        mt1 = fmaxf(mt1, __shfl_xor_sync(0xffffffffu, mt1, 2));

        const float mnew0 = fmaxf(mrow[0], mt0);
        const float mnew1 = fmaxf(mrow[1], mt1);
        const float alpha0 = __expf(mrow[0] - mnew0);
        const float alpha1 = __expf(mrow[1] - mnew1);
        mrow[0] = mnew0; mrow[1] = mnew1;

        float ps0 = 0.f, ps1 = 0.f;
#pragma unroll
        for (int nt = 0; nt < 8; ++nt) {
            sc[nt][0] = __expf(sc[nt][0] - mnew0);
            sc[nt][1] = __expf(sc[nt][1] - mnew0);
            sc[nt][2] = __expf(sc[nt][2] - mnew1);
            sc[nt][3] = __expf(sc[nt][3] - mnew1);
            ps0 += sc[nt][0] + sc[nt][1];
            ps1 += sc[nt][2] + sc[nt][3];
        }
        ps0 += __shfl_xor_sync(0xffffffffu, ps0, 1);
        ps0 += __shfl_xor_sync(0xffffffffu, ps0, 2);
        ps1 += __shfl_xor_sync(0xffffffffu, ps1, 1);
        ps1 += __shfl_xor_sync(0xffffffffu, ps1, 2);
        lrow[0] = lrow[0] * alpha0 + ps0;
        lrow[1] = lrow[1] * alpha1 + ps1;

#pragma unroll
        for (int nt = 0; nt < 8; ++nt) {
            o[nt][0] *= alpha0; o[nt][1] *= alpha0;
            o[nt][2] *= alpha1; o[nt][3] *= alpha1;
        }

#pragma unroll
        for (int j = 0; j < 4; ++j) {
            s.wsum[rl0][kq * 4 + j]     *= alpha0;
            s.wsum[rl0 + 8][kq * 4 + j] *= alpha1;
        }
        __syncwarp();
        if (near) {
#pragma unroll
            for (int nt = 0; nt < 8; ++nt) {
#pragma unroll
                for (int ci = 0; ci < 4; ++ci) {
                    const int row_l = rl0 + ((ci >> 1) << 3);
                    const int delta = (jt * 64 + nt * 8 + 2 * kq + (ci & 1)) - (it * 64 + row_l);
                    if (delta >= -15 && delta <= 0)
                        s.wsum[row_l][delta + 15] += sc[nt][ci];
                }
            }
        }
        __syncwarp();

#pragma unroll
        for (int nt = 0; nt < 8; ++nt) {
            const int c0 = nt * 8 + 2 * kq;
            s.P[rl0][c0]         = __float_as_uint(sc[nt][0]);
            s.P[rl0][c0 + 1]     = __float_as_uint(sc[nt][1]);
            s.P[rl0 + 8][c0]     = __float_as_uint(sc[nt][2]);
            s.P[rl0 + 8][c0 + 1] = __float_as_uint(sc[nt][3]);
        }
        __syncwarp();

#pragma unroll
        for (int ks = 0; ks < 8; ++ks) {
            const int k0 = ks * 8 + kq;
            uint32_t a[4];
            a[0] = s.P[rl0][k0];
            a[1] = s.P[rl0 + 8][k0];
            a[2] = s.P[rl0][k0 + 4];
            a[3] = s.P[rl0 + 8][k0 + 4];
#pragma unroll
            for (int nt = 0; nt < 8; ++nt) {
                uint32_t b[2];
                b[0] = s.V[cur][k0][nt * 8 + ng];
                b[1] = s.V[cur][k0 + 4][nt * 8 + ng];
                mma_tf32(o[nt], a, b);
            }
        }
        __syncthreads();
    }

    for (int i = tid; i < 17 * 16; i += 128) {
        int m = i / 16, dq = i % 16;
        *(float4*)&s.pev[m][dq * 4] = *(const float4*)&pe_v[m * DH + dq * 4];
    }
    __syncthreads();

#pragma unroll
    for (int half = 0; half < 2; ++half) {
        const int rl = rl0 + 8 * half;
        const int tg = it * 64 + rl;
        const float l = lrow[half];
        float wm[16], sumw = 0.f;
#pragma unroll
        for (int m = 0; m < 16; ++m) { wm[m] = s.wsum[rl][m]; sumw += wm[m]; }
        const float w0 = l - sumw;
        const float inv = 1.f / l;
#pragma unroll
        for (int nt = 0; nt < 8; ++nt) {
            const int d0 = nt * 8 + 2 * kq;
            float acc0 = o[nt][half * 2 + 0] + w0 * s.pev[0][d0];
            float acc1 = o[nt][half * 2 + 1] + w0 * s.pev[0][d0 + 1];
#pragma unroll
            for (int m = 1; m <= 16; ++m) {
                acc0 = fmaf(wm[m - 1], s.pev[m][d0], acc0);
                acc1 = fmaf(wm[m - 1], s.pev[m][d0 + 1], acc1);
            }
            float2 ov = make_float2(acc0 * inv, acc1 * inv);
            *(float2*)&g_att[((size_t)(bidx * Tt) + tg) * Uu + h * DH + d0] = ov;
        }
    }
}

// ---------------------------------------------------------------------------
extern "C" void kernel_launch(void* const* d_in, const int* in_sizes, int n_in,
                              void* d_out, int out_size) {
    (void)n_in; (void)out_size;

    int iq, ik, iv, iWq, ibq, iWk, ibk, iWv, ibv, iWo, ibo, ig, ibe, ipk, ipv;
    if (in_sizes[0] == Bb * Tt * Uu) {
        iq = 0; ik = 1; iv = 2; iWq = 3; ibq = 4; iWk = 5; ibk = 6;
        iWv = 7; ibv = 8; iWo = 9; ibo = 10; ig = 11; ibe = 12; ipk = 13; ipv = 14;
    } else if (in_sizes[0] == Uu * Uu) {
        iWk = 0; iWo = 1; iWq = 2; iWv = 3; ibe = 4; ibk = 5; ibo = 6;
        ibq = 7; ibv = 8; ig = 9; ik = 10; ipk = 11; ipv = 12; iq = 13; iv = 14;
    } else {
        ibe = 0; ibk = 1; ibo = 2; ibq = 3; ibv = 4; ig = 5; ik = 6;
        ipk = 7; ipv = 8; iq = 9; iv = 10; iWk = 11; iWo = 12; iWq = 13; iWv = 14;
    }

    const float* q    = (const float*)d_in[iq];
    const float* k    = (const float*)d_in[ik];
    const float* v    = (const float*)d_in[iv];
    const float* Wq   = (const float*)d_in[iWq];
    const float* bq   = (const float*)d_in[ibq];
    const float* Wk   = (const float*)d_in[iWk];
    const float* bk   = (const float*)d_in[ibk];
    const float* Wv   = (const float*)d_in[iWv];
    const float* bv   = (const float*)d_in[ibv];
    const float* Wo   = (const float*)d_in[iWo];
    const float* bo   = (const float*)d_in[ibo];
    const float* gamma= (const float*)d_in[ig];
    const float* beta = (const float*)d_in[ibe];
    const float* pek  = (const float*)d_in[ipk];
    const float* pev  = (const float*)d_in[ipv];
    float* out = (float*)d_out;

    cudaFuncSetAttribute(attn_kernel, cudaFuncAttributeMaxDynamicSharedMemorySize,
                         (int)sizeof(AttnSmem));
    cudaFuncSetAttribute(proj_gemm, cudaFuncAttributeMaxDynamicSharedMemorySize,
                         (int)sizeof(ProjSmem));
    cudaFuncSetAttribute(oproj_ln, cudaFuncAttributeMaxDynamicSharedMemorySize,
                         (int)sizeof(OProjSmem));

    // Q/K/V projections (one launch, z = 0/1/2)
    proj_gemm<<<dim3(4, 64, 3), 256, sizeof(ProjSmem)>>>(
        q, k, v, Wq, Wk, Wv, bq, bk, bv);

    attn_kernel<<<dim3(16, 64), 128, sizeof(AttnSmem)>>>(pek, pev);

    // Fused output projection + residual + LayerNorm -> final output
    oproj_ln<<<128, 256, sizeof(OProjSmem)>>>(Wo, bo, q, gamma, beta, out);
}

// round 11
// speedup vs baseline: 1.0982x; 1.0756x over previous
#include <cuda_runtime.h>
#include <math.h>
#include <stdint.h>

// Problem constants
static constexpr int Bb  = 8;
static constexpr int Tt  = 1024;
static constexpr int Uu  = 512;
static constexpr int DH  = 64;
static constexpr int HB  = 64;           // H*B
static constexpr int MR  = Bb * Tt;      // 8192 rows

// Scratch (device globals: allocation-free rule)
__device__ float g_qh[HB * Tt * DH];
__device__ float g_kh[HB * Tt * DH];
__device__ float g_vh[HB * Tt * DH];
__device__ float g_att[MR * Uu];

// ---------------------------------------------------------------------------
// Helpers
// ---------------------------------------------------------------------------
__device__ __forceinline__ uint32_t f2tf32(float f) {
    uint32_t u;
    asm("cvt.rna.tf32.f32 %0, %1;" : "=r"(u) : "f"(f));
    return u;
}

__device__ __forceinline__ void mma_tf32(float c[4], const uint32_t a[4], const uint32_t b[2]) {
    asm volatile(
        "mma.sync.aligned.m16n8k8.row.col.f32.tf32.tf32.f32 "
        "{%0,%1,%2,%3}, {%4,%5,%6,%7}, {%8,%9}, {%0,%1,%2,%3};"
        : "+f"(c[0]), "+f"(c[1]), "+f"(c[2]), "+f"(c[3])
        : "r"(a[0]), "r"(a[1]), "r"(a[2]), "r"(a[3]), "r"(b[0]), "r"(b[1]));
}

__device__ __forceinline__ void cp16(uint32_t saddr, const void* gptr) {
    asm volatile("cp.async.cg.shared.global [%0], [%1], 16;" :: "r"(saddr), "l"(gptr));
}

__device__ __forceinline__ uint32_t smem_u32(const void* p) {
    uint32_t a;
    asm("{ .reg .u64 t; cvta.to.shared.u64 t, %1; cvt.u32.u64 %0, t; }" : "=r"(a) : "l"(p));
    return a;
}

// ---------------------------------------------------------------------------
// QKV projection GEMM: 128x128 tile, BK=32, 3-stage cp.async, 256 threads
// (8 warps 2x4, warp tile 64x32), 2 CTAs/SM.  Fragments fed to mma as RAW
// fp32 bits (HW truncates to tf32) -> zero CVT in the mainloop.
// z = blockIdx.z selects q/k/v.  Output head-split with bias+relu.
// ---------------------------------------------------------------------------
struct ProjSmem {
    uint32_t As[3][128][36];   // 55296 B
    uint32_t Bs[3][32][136];   // 52224 B
};

__global__ __launch_bounds__(256, 2) void proj_gemm(
    const float* __restrict__ q, const float* __restrict__ k, const float* __restrict__ v,
    const float* __restrict__ Wq, const float* __restrict__ Wk, const float* __restrict__ Wv,
    const float* __restrict__ bq, const float* __restrict__ bk, const float* __restrict__ bv)
{
    extern __shared__ __align__(1024) char smem_raw[];
    ProjSmem& sm = *reinterpret_cast<ProjSmem*>(smem_raw);

    const int z = blockIdx.z;
    const float* A    = (z == 0) ? q  : (z == 1) ? k  : v;
    const float* W    = (z == 0) ? Wq : (z == 1) ? Wk : Wv;
    const float* bias = (z == 0) ? bq : (z == 1) ? bk : bv;

    const int tid  = threadIdx.x;
    const int lane = tid & 31;
    const int wid  = tid >> 5;
    const int wm   = wid >> 2;            // 0..1
    const int wn   = wid & 3;             // 0..3
    const int kq   = lane & 3;
    const int ng   = lane >> 2;
    const int rowBase = blockIdx.y * 128;
    const int nBase   = blockIdx.x * 128;

    const uint32_t aS = smem_u32(&sm.As[0][0][0]);
    const uint32_t bS = smem_u32(&sm.Bs[0][0][0]);

    auto issue = [&](int s, int kt) {
        const int kb = kt * 32;
#pragma unroll
        for (int ii = 0; ii < 4; ++ii) {
            const int idx = tid + ii * 256;       // A: 128 rows x 8 quads
            const int r = idx >> 3, q4 = idx & 7;
            cp16(aS + (((s * 128 + r) * 36 + q4 * 4) << 2),
                 &A[(size_t)(rowBase + r) * Uu + kb + q4 * 4]);
        }
#pragma unroll
        for (int ii = 0; ii < 4; ++ii) {
            const int idx = tid + ii * 256;       // B: 32 krows x 32 quads
            const int kr = idx >> 5, n4 = idx & 31;
            cp16(bS + (((s * 32 + kr) * 136 + n4 * 4) << 2),
                 &W[(size_t)(kb + kr) * Uu + nBase + n4 * 4]);
        }
        asm volatile("cp.async.commit_group;");
    };

    constexpr int NIT = Uu / 32;   // 16
    issue(0, 0);
    issue(1, 1);

    const int r0 = wm * 64 + ng;
    const int n0 = wn * 32 + ng;

    float c[4][4][4] = {};

    for (int kb = 0; kb < NIT; ++kb) {
        const int cur = kb % 3;
        if (kb + 1 < NIT) asm volatile("cp.async.wait_group 1;");
        else              asm volatile("cp.async.wait_group 0;");
        __syncthreads();

#pragma unroll
        for (int ks = 0; ks < 4; ++ks) {
            const int k0 = ks * 8 + kq;
            uint32_t a[4][4];
#pragma unroll
            for (int mt = 0; mt < 4; ++mt) {
                const int rr = r0 + mt * 16;
                a[mt][0] = sm.As[cur][rr][k0];
                a[mt][1] = sm.As[cur][rr + 8][k0];
                a[mt][2] = sm.As[cur][rr][k0 + 4];
                a[mt][3] = sm.As[cur][rr + 8][k0 + 4];
            }
#pragma unroll
            for (int nt = 0; nt < 4; ++nt) {
                uint32_t b[2];
                b[0] = sm.Bs[cur][k0][n0 + nt * 8];
                b[1] = sm.Bs[cur][k0 + 4][n0 + nt * 8];
#pragma unroll
                for (int mt = 0; mt < 4; ++mt)
                    mma_tf32(c[mt][nt], a[mt], b);
            }
        }

        if (kb + 2 < NIT) issue((kb + 2) % 3, kb + 2);
    }

    // Epilogue: bias + relu, head-split scatter
    float* dst = (z == 0) ? g_qh : (z == 1) ? g_kh : g_vh;
#pragma unroll
    for (int mt = 0; mt < 4; ++mt) {
        const int rbase = rowBase + wm * 64 + mt * 16 + ng;
#pragma unroll
        for (int nt = 0; nt < 4; ++nt) {
            const int n = nBase + wn * 32 + nt * 8 + 2 * kq;
            const float2 bi = *(const float2*)&bias[n];
            const int h = n >> 6, d = n & 63;
#pragma unroll
            for (int half = 0; half < 2; ++half) {
                const int m = rbase + half * 8;
                const int bidx = m >> 10, t = m & 1023;
                float2 o;
                o.x = fmaxf(c[mt][nt][half * 2 + 0] + bi.x, 0.f);
                o.y = fmaxf(c[mt][nt][half * 2 + 1] + bi.y, 0.f);
                *(float2*)&dst[((size_t)(h * 8 + bidx) * Tt + t) * DH + d] = o;
            }
        }
    }
}

// ---------------------------------------------------------------------------
// Fused out-projection + residual + LayerNorm, 4-stage cp.async.
// One block = 64 full rows (tile 64x512).  Raw-bit tf32 fragments (no CVT).
// ---------------------------------------------------------------------------
struct OProjSmem {
    uint32_t As[4][64][20];     // 20480 B
    uint32_t Bs[4][16][520];    // 133120 B
    float part[2][8][64];       // 4096 B
    float mu[64];
    float rs[64];
};

__global__ __launch_bounds__(256) void oproj_ln(
    const float* __restrict__ Wo, const float* __restrict__ bo,
    const float* __restrict__ res,
    const float* __restrict__ gamma, const float* __restrict__ beta,
    float* __restrict__ out)
{
    extern __shared__ __align__(1024) char smem_raw[];
    OProjSmem& sm = *reinterpret_cast<OProjSmem*>(smem_raw);

    const int tid  = threadIdx.x;
    const int lane = tid & 31;
    const int w    = tid >> 5;
    const int kq   = lane & 3;
    const int ng   = lane >> 2;
    const int rowBase = blockIdx.x * 64;

    const uint32_t aS = smem_u32(&sm.As[0][0][0]);
    const uint32_t bS = smem_u32(&sm.Bs[0][0][0]);

    auto issue = [&](int s, int kt) {
        const int kb = kt * 16;
        {
            const int r = tid >> 2, q4 = tid & 3;
            cp16(aS + (((s * 64 + r) * 20 + q4 * 4) << 2),
                 &g_att[(size_t)(rowBase + r) * Uu + kb + q4 * 4]);
        }
#pragma unroll
        for (int ii = 0; ii < 8; ++ii) {
            const int idx = tid + ii * 256;
            const int kr = idx >> 7, n4 = idx & 127;
            cp16(bS + (((s * 16 + kr) * 520 + n4 * 4) << 2),
                 &Wo[(size_t)(kb + kr) * Uu + n4 * 4]);
        }
        asm volatile("cp.async.commit_group;");
    };

    constexpr int NIT = Uu / 16;   // 32
    issue(0, 0);
    issue(1, 1);
    issue(2, 2);

    float c[4][8][4] = {};

    for (int kb = 0; kb < NIT; ++kb) {
        const int cur = kb & 3;
        if      (kb + 2 < NIT) asm volatile("cp.async.wait_group 2;");
        else if (kb + 1 < NIT) asm volatile("cp.async.wait_group 1;");
        else                   asm volatile("cp.async.wait_group 0;");
        __syncthreads();

#pragma unroll
        for (int ks = 0; ks < 2; ++ks) {
            const int k0 = ks * 8 + kq;
            uint32_t a[4][4];
#pragma unroll
            for (int mt = 0; mt < 4; ++mt) {
                const int r0 = mt * 16 + ng;
                a[mt][0] = sm.As[cur][r0][k0];
                a[mt][1] = sm.As[cur][r0 + 8][k0];
                a[mt][2] = sm.As[cur][r0][k0 + 4];
                a[mt][3] = sm.As[cur][r0 + 8][k0 + 4];
            }
#pragma unroll
            for (int nt = 0; nt < 8; ++nt) {
                uint32_t b[2];
                const int n0 = w * 64 + nt * 8 + ng;
                b[0] = sm.Bs[cur][k0][n0];
                b[1] = sm.Bs[cur][k0 + 4][n0];
#pragma unroll
                for (int mt = 0; mt < 4; ++mt)
                    mma_tf32(c[mt][nt], a[mt], b);
            }
        }

        if (kb + 3 < NIT) issue((kb + 3) & 3, kb + 3);
    }

    // ---- bias + relu + residual; accumulate per-row partial stats ----
    float psum[8] = {}, psq[8] = {};
#pragma unroll
    for (int mt = 0; mt < 4; ++mt) {
#pragma unroll
        for (int half = 0; half < 2; ++half) {
            const int m = rowBase + mt * 16 + ng + half * 8;
            const int slot = mt * 2 + half;
#pragma unroll
            for (int nt = 0; nt < 8; ++nt) {
                const int n = w * 64 + nt * 8 + 2 * kq;
                const float2 bi = *(const float2*)&bo[n];
                const float2 r2 = *(const float2*)&res[(size_t)m * Uu + n];
                float vx = fmaxf(c[mt][nt][half * 2 + 0] + bi.x, 0.f) + r2.x;
                float vy = fmaxf(c[mt][nt][half * 2 + 1] + bi.y, 0.f) + r2.y;
                c[mt][nt][half * 2 + 0] = vx;
                c[mt][nt][half * 2 + 1] = vy;
                psum[slot] += vx + vy;
                psq[slot]  += vx * vx + vy * vy;
            }
        }
    }
#pragma unroll
    for (int slot = 0; slot < 8; ++slot) {
        psum[slot] += __shfl_xor_sync(0xffffffffu, psum[slot], 1);
        psum[slot] += __shfl_xor_sync(0xffffffffu, psum[slot], 2);
        psq[slot]  += __shfl_xor_sync(0xffffffffu, psq[slot], 1);
        psq[slot]  += __shfl_xor_sync(0xffffffffu, psq[slot], 2);
    }
    if (kq == 0) {
#pragma unroll
        for (int mt = 0; mt < 4; ++mt)
#pragma unroll
            for (int half = 0; half < 2; ++half) {
                const int rl = mt * 16 + ng + half * 8;
                sm.part[0][w][rl] = psum[mt * 2 + half];
                sm.part[1][w][rl] = psq[mt * 2 + half];
            }
    }
    __syncthreads();

    if (tid < 64) {
        float su = 0.f, sq = 0.f;
#pragma unroll
        for (int wi = 0; wi < 8; ++wi) {
            su += sm.part[0][wi][tid];
            sq += sm.part[1][wi][tid];
        }
        const float mu = su * (1.f / Uu);
        const float var = sq * (1.f / Uu) - mu * mu;
        sm.mu[tid] = mu;
        sm.rs[tid] = rsqrtf(var + 1e-3f);
    }
    __syncthreads();

#pragma unroll
    for (int mt = 0; mt < 4; ++mt) {
#pragma unroll
        for (int half = 0; half < 2; ++half) {
            const int rl = mt * 16 + ng + half * 8;
            const int m = rowBase + rl;
            const float mu = sm.mu[rl];
            const float rstd = sm.rs[rl];
#pragma unroll
            for (int nt = 0; nt < 8; ++nt) {
                const int n = w * 64 + nt * 8 + 2 * kq;
                const float2 g2 = *(const float2*)&gamma[n];
                const float2 b2 = *(const float2*)&beta[n];
                float2 o;
                o.x = (c[mt][nt][half * 2 + 0] - mu) * rstd * g2.x + b2.x;
                o.y = (c[mt][nt][half * 2 + 1] - mu) * rstd * g2.y + b2.y;
                *(float2*)&out[(size_t)m * Uu + n] = o;
            }
        }
    }
}

// ---------------------------------------------------------------------------
// Tensor-core flash attention (validated round-6/7 kernel, unchanged).
// ---------------------------------------------------------------------------
struct AttnSmem {
    uint32_t K[2][64][68];
    uint32_t V[2][64][72];
    union { uint32_t Q[64][68]; float pev[17][68]; };
    union { uint32_t P[64][68]; float pek[17][68]; };
    float qrel[64][17];
    float wsum[64][16];
};

__global__ __launch_bounds__(128) void attn_kernel(
    const float* __restrict__ pe_k, const float* __restrict__ pe_v)
{
    extern __shared__ __align__(16) char smem_raw[];
    AttnSmem& s = *reinterpret_cast<AttnSmem*>(smem_raw);

    const int tid  = threadIdx.x;
    const int lane = tid & 31;
    const int w    = tid >> 5;
    const int kq   = lane & 3;
    const int ng   = lane >> 2;
    const int it   = 15 - (int)blockIdx.x;
    const int hb   = blockIdx.y;
    const int h = hb >> 3, bidx = hb & 7;

    const float* qbase = g_qh + (size_t)hb * Tt * DH;
    const float* kbase = g_kh + (size_t)hb * Tt * DH;
    const float* vbase = g_vh + (size_t)hb * Tt * DH;

    const uint32_t kS = smem_u32(&s.K[0][0][0]);
    const uint32_t vS = smem_u32(&s.V[0][0][0]);

    auto issue_tile = [&](int buf, int jt) {
#pragma unroll
        for (int ii = 0; ii < 8; ++ii) {
            const int i = tid + ii * 128;
            const int c = i >> 4, dq = i & 15;
            cp16(kS + (((buf * 64 + c) * 68 + dq * 4) << 2),
                 &kbase[(size_t)(jt * 64 + c) * DH + dq * 4]);
            cp16(vS + (((buf * 64 + c) * 72 + dq * 4) << 2),
                 &vbase[(size_t)(jt * 64 + c) * DH + dq * 4]);
        }
        asm volatile("cp.async.commit_group;");
    };

    issue_tile(0, 0);

    for (int i = tid; i < 1024; i += 128) {
        int r = i >> 4, dq = i & 15;
        float4 a = *(const float4*)&qbase[(size_t)(it * 64 + r) * DH + dq * 4];
        s.Q[r][dq * 4 + 0] = f2tf32(a.x * 0.125f);
        s.Q[r][dq * 4 + 1] = f2tf32(a.y * 0.125f);
        s.Q[r][dq * 4 + 2] = f2tf32(a.z * 0.125f);
        s.Q[r][dq * 4 + 3] = f2tf32(a.w * 0.125f);
    }
    for (int i = tid; i < 17 * 16; i += 128) {
        int m = i / 16, dq = i % 16;
        *(float4*)&s.pek[m][dq * 4] = *(const float4*)&pe_k[m * DH + dq * 4];
    }
    for (int i = tid; i < 1024; i += 128)
        (&s.wsum[0][0])[i] = 0.f;
    __syncthreads();

    for (int i = tid; i < 64 * 17; i += 128) {
        int r = i / 17, m = i % 17;
        float acc = 0.f;
#pragma unroll 16
        for (int d = 0; d < DH; ++d)
            acc = fmaf(__uint_as_float(s.Q[r][d]), s.pek[m][d], acc);
        s.qrel[r][m] = acc;
    }
    __syncthreads();

    const int rl0 = w * 16 + ng;
    const float qrel0_0 = s.qrel[rl0][0];
    const float qrel0_1 = s.qrel[rl0 + 8][0];

    float o[8][4] = {};
    float mrow[2] = {-1e30f, -1e30f};
    float lrow[2] = {};

    for (int jt = 0; jt <= it; ++jt) {
        const int cur = jt & 1;
        if (jt < it) {
            issue_tile(cur ^ 1, jt + 1);
            asm volatile("cp.async.wait_group 1;");
        } else {
            asm volatile("cp.async.wait_group 0;");
        }
        __syncthreads();

        float sc[8][4] = {};
#pragma unroll
        for (int ks = 0; ks < 8; ++ks) {
            const int k0 = ks * 8 + kq;
            uint32_t a[4];
            a[0] = s.Q[rl0][k0];
            a[1] = s.Q[rl0 + 8][k0];
            a[2] = s.Q[rl0][k0 + 4];
            a[3] = s.Q[rl0 + 8][k0 + 4];
#pragma unroll
            for (int nt = 0; nt < 8; ++nt) {
                uint32_t b[2];
                b[0] = s.K[cur][nt * 8 + ng][k0];
                b[1] = s.K[cur][nt * 8 + ng][k0 + 4];
                mma_tf32(sc[nt], a, b);
            }
        }

        const bool near = (jt >= it - 1);
        if (near) {
#pragma unroll
            for (int nt = 0; nt < 8; ++nt) {
#pragma unroll
                for (int ci = 0; ci < 4; ++ci) {
                    const int row_l = rl0 + ((ci >> 1) << 3);
                    const int tg = it * 64 + row_l;
                    const int sg = jt * 64 + nt * 8 + 2 * kq + (ci & 1);
                    const int delta = sg - tg;
                    if (delta > 0) sc[nt][ci] = -1e30f;
                    else {
                        int mi = delta + 16; if (mi < 0) mi = 0;
                        sc[nt][ci] += s.qrel[row_l][mi];
                    }
                }
            }
        } else {
#pragma unroll
            for (int nt = 0; nt < 8; ++nt) {
                sc[nt][0] += qrel0_0;
                sc[nt][1] += qrel0_0;
                sc[nt][2] += qrel0_1;
                sc[nt][3] += qrel0_1;
            }
        }

        float mt0 = -1e30f, mt1 = -1e30f;
#pragma unroll
        for (int nt = 0; nt < 8; ++nt) {
            mt0 = fmaxf(mt0, fmaxf(sc[nt][0], sc[nt][1]));
            mt1 = fmaxf(mt1, fmaxf(sc[nt][2], sc[nt][3]));
        }
        mt0 = fmaxf(mt0, __shfl_xor_sync(0xffffffffu, mt0, 1));
        mt0 = fmaxf(mt0, __shfl_xor_sync(0xffffffffu, mt0, 2));
        mt1 = fmaxf(mt1, __shfl_xor_sync(0xffffffffu, mt1, 1));
        mt1 = fmaxf(mt1, __shfl_xor_sync(0xffffffffu, mt1, 2));

        const float mnew0 = fmaxf(mrow[0], mt0);
        const float mnew1 = fmaxf(mrow[1], mt1);
        const float alpha0 = __expf(mrow[0] - mnew0);
        const float alpha1 = __expf(mrow[1] - mnew1);
        mrow[0] = mnew0; mrow[1] = mnew1;

        float ps0 = 0.f, ps1 = 0.f;
#pragma unroll
        for (int nt = 0; nt < 8; ++nt) {
            sc[nt][0] = __expf(sc[nt][0] - mnew0);
            sc[nt][1] = __expf(sc[nt][1] - mnew0);
            sc[nt][2] = __expf(sc[nt][2] - mnew1);
            sc[nt][3] = __expf(sc[nt][3] - mnew1);
            ps0 += sc[nt][0] + sc[nt][1];
            ps1 += sc[nt][2] + sc[nt][3];
        }
        ps0 += __shfl_xor_sync(0xffffffffu, ps0, 1);
        ps0 += __shfl_xor_sync(0xffffffffu, ps0, 2);
        ps1 += __shfl_xor_sync(0xffffffffu, ps1, 1);
        ps1 += __shfl_xor_sync(0xffffffffu, ps1, 2);
        lrow[0] = lrow[0] * alpha0 + ps0;
        lrow[1] = lrow[1] * alpha1 + ps1;

#pragma unroll
        for (int nt = 0; nt < 8; ++nt) {
            o[nt][0] *= alpha0; o[nt][1] *= alpha0;
            o[nt][2] *= alpha1; o[nt][3] *= alpha1;
        }

#pragma unroll
        for (int j = 0; j < 4; ++j) {
            s.wsum[rl0][kq * 4 + j]     *= alpha0;
            s.wsum[rl0 + 8][kq * 4 + j] *= alpha1;
        }
        __syncwarp();
        if (near) {
#pragma unroll
            for (int nt = 0; nt < 8; ++nt) {
#pragma unroll
                for (int ci = 0; ci < 4; ++ci) {
                    const int row_l = rl0 + ((ci >> 1) << 3);
                    const int delta = (jt * 64 + nt * 8 + 2 * kq + (ci & 1)) - (it * 64 + row_l);
                    if (delta >= -15 && delta <= 0)
                        s.wsum[row_l][delta + 15] += sc[nt][ci];
                }
            }
        }
        __syncwarp();

#pragma unroll
        for (int nt = 0; nt < 8; ++nt) {
            const int c0 = nt * 8 + 2 * kq;
            s.P[rl0][c0]         = __float_as_uint(sc[nt][0]);
            s.P[rl0][c0 + 1]     = __float_as_uint(sc[nt][1]);
            s.P[rl0 + 8][c0]     = __float_as_uint(sc[nt][2]);
            s.P[rl0 + 8][c0 + 1] = __float_as_uint(sc[nt][3]);
        }
        __syncwarp();

#pragma unroll
        for (int ks = 0; ks < 8; ++ks) {
            const int k0 = ks * 8 + kq;
            uint32_t a[4];
            a[0] = s.P[rl0][k0];
            a[1] = s.P[rl0 + 8][k0];
            a[2] = s.P[rl0][k0 + 4];
            a[3] = s.P[rl0 + 8][k0 + 4];
#pragma unroll
            for (int nt = 0; nt < 8; ++nt) {
                uint32_t b[2];
                b[0] = s.V[cur][k0][nt * 8 + ng];
                b[1] = s.V[cur][k0 + 4][nt * 8 + ng];
                mma_tf32(o[nt], a, b);
            }
        }
        __syncthreads();
    }

    for (int i = tid; i < 17 * 16; i += 128) {
        int m = i / 16, dq = i % 16;
        *(float4*)&s.pev[m][dq * 4] = *(const float4*)&pe_v[m * DH + dq * 4];
    }
    __syncthreads();

#pragma unroll
    for (int half = 0; half < 2; ++half) {
        const int rl = rl0 + 8 * half;
        const int tg = it * 64 + rl;
        const float l = lrow[half];
        float wm[16], sumw = 0.f;
#pragma unroll
        for (int m = 0; m < 16; ++m) { wm[m] = s.wsum[rl][m]; sumw += wm[m]; }
        const float w0 = l - sumw;
        const float inv = 1.f / l;
#pragma unroll
        for (int nt = 0; nt < 8; ++nt) {
            const int d0 = nt * 8 + 2 * kq;
            float acc0 = o[nt][half * 2 + 0] + w0 * s.pev[0][d0];
            float acc1 = o[nt][half * 2 + 1] + w0 * s.pev[0][d0 + 1];
#pragma unroll
            for (int m = 1; m <= 16; ++m) {
                acc0 = fmaf(wm[m - 1], s.pev[m][d0], acc0);
                acc1 = fmaf(wm[m - 1], s.pev[m][d0 + 1], acc1);
            }
            float2 ov = make_float2(acc0 * inv, acc1 * inv);
            *(float2*)&g_att[((size_t)(bidx * Tt) + tg) * Uu + h * DH + d0] = ov;
        }
    }
}

// ---------------------------------------------------------------------------
extern "C" void kernel_launch(void* const* d_in, const int* in_sizes, int n_in,
                              void* d_out, int out_size) {
    (void)n_in; (void)out_size;

    int iq, ik, iv, iWq, ibq, iWk, ibk, iWv, ibv, iWo, ibo, ig, ibe, ipk, ipv;
    if (in_sizes[0] == Bb * Tt * Uu) {
        iq = 0; ik = 1; iv = 2; iWq = 3; ibq = 4; iWk = 5; ibk = 6;
        iWv = 7; ibv = 8; iWo = 9; ibo = 10; ig = 11; ibe = 12; ipk = 13; ipv = 14;
    } else if (in_sizes[0] == Uu * Uu) {
        iWk = 0; iWo = 1; iWq = 2; iWv = 3; ibe = 4; ibk = 5; ibo = 6;
        ibq = 7; ibv = 8; ig = 9; ik = 10; ipk = 11; ipv = 12; iq = 13; iv = 14;
    } else {
        ibe = 0; ibk = 1; ibo = 2; ibq = 3; ibv = 4; ig = 5; ik = 6;
        ipk = 7; ipv = 8; iq = 9; iv = 10; iWk = 11; iWo = 12; iWq = 13; iWv = 14;
    }

    const float* q    = (const float*)d_in[iq];
    const float* k    = (const float*)d_in[ik];
    const float* v    = (const float*)d_in[iv];
    const float* Wq   = (const float*)d_in[iWq];
    const float* bq   = (const float*)d_in[ibq];
    const float* Wk   = (const float*)d_in[iWk];
    const float* bk   = (const float*)d_in[ibk];
    const float* Wv   = (const float*)d_in[iWv];
    const float* bv   = (const float*)d_in[ibv];
    const float* Wo   = (const float*)d_in[iWo];
    const float* bo   = (const float*)d_in[ibo];
    const float* gamma= (const float*)d_in[ig];
    const float* beta = (const float*)d_in[ibe];
    const float* pek  = (const float*)d_in[ipk];
    const float* pev  = (const float*)d_in[ipv];
    float* out = (float*)d_out;

    cudaFuncSetAttribute(attn_kernel, cudaFuncAttributeMaxDynamicSharedMemorySize,
                         (int)sizeof(AttnSmem));
    cudaFuncSetAttribute(proj_gemm, cudaFuncAttributeMaxDynamicSharedMemorySize,
                         (int)sizeof(ProjSmem));
    cudaFuncSetAttribute(oproj_ln, cudaFuncAttributeMaxDynamicSharedMemorySize,
                         (int)sizeof(OProjSmem));

    // Q/K/V projections (one launch, z = 0/1/2)
    proj_gemm<<<dim3(4, 64, 3), 256, sizeof(ProjSmem)>>>(
        q, k, v, Wq, Wk, Wv, bq, bk, bv);

    attn_kernel<<<dim3(16, 64), 128, sizeof(AttnSmem)>>>(pek, pev);

    // Fused output projection + residual + LayerNorm -> final output
    oproj_ln<<<128, 256, sizeof(OProjSmem)>>>(Wo, bo, q, gamma, beta, out);
}

// round 12
// speedup vs baseline: 1.1081x; 1.0091x over previous
#include <cuda_runtime.h>
#include <math.h>
#include <stdint.h>

// Problem constants
static constexpr int Bb  = 8;
static constexpr int Tt  = 1024;
static constexpr int Uu  = 512;
static constexpr int DH  = 64;
static constexpr int HB  = 64;           // H*B
static constexpr int MR  = Bb * Tt;      // 8192 rows

// Scratch (device globals: allocation-free rule)
__device__ float g_qh[HB * Tt * DH];
__device__ float g_kh[HB * Tt * DH];
__device__ float g_vh[HB * Tt * DH];
__device__ float g_att[MR * Uu];

// ---------------------------------------------------------------------------
// Helpers
// ---------------------------------------------------------------------------
__device__ __forceinline__ uint32_t f2tf32(float f) {
    uint32_t u;
    asm("cvt.rna.tf32.f32 %0, %1;" : "=r"(u) : "f"(f));
    return u;
}

__device__ __forceinline__ void mma_tf32(float c[4], const uint32_t a[4], const uint32_t b[2]) {
    asm volatile(
        "mma.sync.aligned.m16n8k8.row.col.f32.tf32.tf32.f32 "
        "{%0,%1,%2,%3}, {%4,%5,%6,%7}, {%8,%9}, {%0,%1,%2,%3};"
        : "+f"(c[0]), "+f"(c[1]), "+f"(c[2]), "+f"(c[3])
        : "r"(a[0]), "r"(a[1]), "r"(a[2]), "r"(a[3]), "r"(b[0]), "r"(b[1]));
}

__device__ __forceinline__ void cp16(uint32_t saddr, const void* gptr) {
    asm volatile("cp.async.cg.shared.global [%0], [%1], 16;" :: "r"(saddr), "l"(gptr));
}

__device__ __forceinline__ uint32_t smem_u32(const void* p) {
    uint32_t a;
    asm("{ .reg .u64 t; cvta.to.shared.u64 t, %1; cvt.u32.u64 %0, t; }" : "=r"(a) : "l"(p));
    return a;
}

// ---------------------------------------------------------------------------
// QKV projection GEMM: 128x128 tile, BK=32, 3-stage cp.async, 256 threads
// (8 warps 2x4, warp tile 64x32), 2 CTAs/SM.  Raw-bit tf32 fragments.
// ---------------------------------------------------------------------------
struct ProjSmem {
    uint32_t As[3][128][36];   // 55296 B
    uint32_t Bs[3][32][136];   // 52224 B
};

__global__ __launch_bounds__(256, 2) void proj_gemm(
    const float* __restrict__ q, const float* __restrict__ k, const float* __restrict__ v,
    const float* __restrict__ Wq, const float* __restrict__ Wk, const float* __restrict__ Wv,
    const float* __restrict__ bq, const float* __restrict__ bk, const float* __restrict__ bv)
{
    extern __shared__ __align__(1024) char smem_raw[];
    ProjSmem& sm = *reinterpret_cast<ProjSmem*>(smem_raw);

    const int z = blockIdx.z;
    const float* A    = (z == 0) ? q  : (z == 1) ? k  : v;
    const float* W    = (z == 0) ? Wq : (z == 1) ? Wk : Wv;
    const float* bias = (z == 0) ? bq : (z == 1) ? bk : bv;

    const int tid  = threadIdx.x;
    const int lane = tid & 31;
    const int wid  = tid >> 5;
    const int wm   = wid >> 2;            // 0..1
    const int wn   = wid & 3;             // 0..3
    const int kq   = lane & 3;
    const int ng   = lane >> 2;
    const int rowBase = blockIdx.y * 128;
    const int nBase   = blockIdx.x * 128;

    const uint32_t aS = smem_u32(&sm.As[0][0][0]);
    const uint32_t bS = smem_u32(&sm.Bs[0][0][0]);

    auto issue = [&](int s, int kt) {
        const int kb = kt * 32;
#pragma unroll
        for (int ii = 0; ii < 4; ++ii) {
            const int idx = tid + ii * 256;       // A: 128 rows x 8 quads
            const int r = idx >> 3, q4 = idx & 7;
            cp16(aS + (((s * 128 + r) * 36 + q4 * 4) << 2),
                 &A[(size_t)(rowBase + r) * Uu + kb + q4 * 4]);
        }
#pragma unroll
        for (int ii = 0; ii < 4; ++ii) {
            const int idx = tid + ii * 256;       // B: 32 krows x 32 quads
            const int kr = idx >> 5, n4 = idx & 31;
            cp16(bS + (((s * 32 + kr) * 136 + n4 * 4) << 2),
                 &W[(size_t)(kb + kr) * Uu + nBase + n4 * 4]);
        }
        asm volatile("cp.async.commit_group;");
    };

    constexpr int NIT = Uu / 32;   // 16
    issue(0, 0);
    issue(1, 1);

    const int r0 = wm * 64 + ng;
    const int n0 = wn * 32 + ng;

    float c[4][4][4] = {};

    for (int kb = 0; kb < NIT; ++kb) {
        const int cur = kb % 3;
        if (kb + 1 < NIT) asm volatile("cp.async.wait_group 1;");
        else              asm volatile("cp.async.wait_group 0;");
        __syncthreads();

#pragma unroll
        for (int ks = 0; ks < 4; ++ks) {
            const int k0 = ks * 8 + kq;
            uint32_t a[4][4];
#pragma unroll
            for (int mt = 0; mt < 4; ++mt) {
                const int rr = r0 + mt * 16;
                a[mt][0] = sm.As[cur][rr][k0];
                a[mt][1] = sm.As[cur][rr + 8][k0];
                a[mt][2] = sm.As[cur][rr][k0 + 4];
                a[mt][3] = sm.As[cur][rr + 8][k0 + 4];
            }
#pragma unroll
            for (int nt = 0; nt < 4; ++nt) {
                uint32_t b[2];
                b[0] = sm.Bs[cur][k0][n0 + nt * 8];
                b[1] = sm.Bs[cur][k0 + 4][n0 + nt * 8];
#pragma unroll
                for (int mt = 0; mt < 4; ++mt)
                    mma_tf32(c[mt][nt], a[mt], b);
            }
        }

        if (kb + 2 < NIT) issue((kb + 2) % 3, kb + 2);
    }

    // Epilogue: bias + relu, head-split scatter
    float* dst = (z == 0) ? g_qh : (z == 1) ? g_kh : g_vh;
#pragma unroll
    for (int mt = 0; mt < 4; ++mt) {
        const int rbase = rowBase + wm * 64 + mt * 16 + ng;
#pragma unroll
        for (int nt = 0; nt < 4; ++nt) {
            const int n = nBase + wn * 32 + nt * 8 + 2 * kq;
            const float2 bi = *(const float2*)&bias[n];
            const int h = n >> 6, d = n & 63;
#pragma unroll
            for (int half = 0; half < 2; ++half) {
                const int m = rbase + half * 8;
                const int bidx = m >> 10, t = m & 1023;
                float2 o;
                o.x = fmaxf(c[mt][nt][half * 2 + 0] + bi.x, 0.f);
                o.y = fmaxf(c[mt][nt][half * 2 + 1] + bi.y, 0.f);
                *(float2*)&dst[((size_t)(h * 8 + bidx) * Tt + t) * DH + d] = o;
            }
        }
    }
}

// ---------------------------------------------------------------------------
// Fused out-projection + residual + LayerNorm, 4-stage cp.async (r11 winner).
// ---------------------------------------------------------------------------
struct OProjSmem {
    uint32_t As[4][64][20];     // 20480 B
    uint32_t Bs[4][16][520];    // 133120 B
    float part[2][8][64];       // 4096 B
    float mu[64];
    float rs[64];
};

__global__ __launch_bounds__(256) void oproj_ln(
    const float* __restrict__ Wo, const float* __restrict__ bo,
    const float* __restrict__ res,
    const float* __restrict__ gamma, const float* __restrict__ beta,
    float* __restrict__ out)
{
    extern __shared__ __align__(1024) char smem_raw[];
    OProjSmem& sm = *reinterpret_cast<OProjSmem*>(smem_raw);

    const int tid  = threadIdx.x;
    const int lane = tid & 31;
    const int w    = tid >> 5;
    const int kq   = lane & 3;
    const int ng   = lane >> 2;
    const int rowBase = blockIdx.x * 64;

    const uint32_t aS = smem_u32(&sm.As[0][0][0]);
    const uint32_t bS = smem_u32(&sm.Bs[0][0][0]);

    auto issue = [&](int s, int kt) {
        const int kb = kt * 16;
        {
            const int r = tid >> 2, q4 = tid & 3;
            cp16(aS + (((s * 64 + r) * 20 + q4 * 4) << 2),
                 &g_att[(size_t)(rowBase + r) * Uu + kb + q4 * 4]);
        }
#pragma unroll
        for (int ii = 0; ii < 8; ++ii) {
            const int idx = tid + ii * 256;
            const int kr = idx >> 7, n4 = idx & 127;
            cp16(bS + (((s * 16 + kr) * 520 + n4 * 4) << 2),
                 &Wo[(size_t)(kb + kr) * Uu + n4 * 4]);
        }
        asm volatile("cp.async.commit_group;");
    };

    constexpr int NIT = Uu / 16;   // 32
    issue(0, 0);
    issue(1, 1);
    issue(2, 2);

    float c[4][8][4] = {};

    for (int kb = 0; kb < NIT; ++kb) {
        const int cur = kb & 3;
        if      (kb + 2 < NIT) asm volatile("cp.async.wait_group 2;");
        else if (kb + 1 < NIT) asm volatile("cp.async.wait_group 1;");
        else                   asm volatile("cp.async.wait_group 0;");
        __syncthreads();

#pragma unroll
        for (int ks = 0; ks < 2; ++ks) {
            const int k0 = ks * 8 + kq;
            uint32_t a[4][4];
#pragma unroll
            for (int mt = 0; mt < 4; ++mt) {
                const int r0 = mt * 16 + ng;
                a[mt][0] = sm.As[cur][r0][k0];
                a[mt][1] = sm.As[cur][r0 + 8][k0];
                a[mt][2] = sm.As[cur][r0][k0 + 4];
                a[mt][3] = sm.As[cur][r0 + 8][k0 + 4];
            }
#pragma unroll
            for (int nt = 0; nt < 8; ++nt) {
                uint32_t b[2];
                const int n0 = w * 64 + nt * 8 + ng;
                b[0] = sm.Bs[cur][k0][n0];
                b[1] = sm.Bs[cur][k0 + 4][n0];
#pragma unroll
                for (int mt = 0; mt < 4; ++mt)
                    mma_tf32(c[mt][nt], a[mt], b);
            }
        }

        if (kb + 3 < NIT) issue((kb + 3) & 3, kb + 3);
    }

    // ---- bias + relu + residual; accumulate per-row partial stats ----
    float psum[8] = {}, psq[8] = {};
#pragma unroll
    for (int mt = 0; mt < 4; ++mt) {
#pragma unroll
        for (int half = 0; half < 2; ++half) {
            const int m = rowBase + mt * 16 + ng + half * 8;
            const int slot = mt * 2 + half;
#pragma unroll
            for (int nt = 0; nt < 8; ++nt) {
                const int n = w * 64 + nt * 8 + 2 * kq;
                const float2 bi = *(const float2*)&bo[n];
                const float2 r2 = *(const float2*)&res[(size_t)m * Uu + n];
                float vx = fmaxf(c[mt][nt][half * 2 + 0] + bi.x, 0.f) + r2.x;
                float vy = fmaxf(c[mt][nt][half * 2 + 1] + bi.y, 0.f) + r2.y;
                c[mt][nt][half * 2 + 0] = vx;
                c[mt][nt][half * 2 + 1] = vy;
                psum[slot] += vx + vy;
                psq[slot]  += vx * vx + vy * vy;
            }
        }
    }
#pragma unroll
    for (int slot = 0; slot < 8; ++slot) {
        psum[slot] += __shfl_xor_sync(0xffffffffu, psum[slot], 1);
        psum[slot] += __shfl_xor_sync(0xffffffffu, psum[slot], 2);
        psq[slot]  += __shfl_xor_sync(0xffffffffu, psq[slot], 1);
        psq[slot]  += __shfl_xor_sync(0xffffffffu, psq[slot], 2);
    }
    if (kq == 0) {
#pragma unroll
        for (int mt = 0; mt < 4; ++mt)
#pragma unroll
            for (int half = 0; half < 2; ++half) {
                const int rl = mt * 16 + ng + half * 8;
                sm.part[0][w][rl] = psum[mt * 2 + half];
                sm.part[1][w][rl] = psq[mt * 2 + half];
            }
    }
    __syncthreads();

    if (tid < 64) {
        float su = 0.f, sq = 0.f;
#pragma unroll
        for (int wi = 0; wi < 8; ++wi) {
            su += sm.part[0][wi][tid];
            sq += sm.part[1][wi][tid];
        }
        const float mu = su * (1.f / Uu);
        const float var = sq * (1.f / Uu) - mu * mu;
        sm.mu[tid] = mu;
        sm.rs[tid] = rsqrtf(var + 1e-3f);
    }
    __syncthreads();

#pragma unroll
    for (int mt = 0; mt < 4; ++mt) {
#pragma unroll
        for (int half = 0; half < 2; ++half) {
            const int rl = mt * 16 + ng + half * 8;
            const int m = rowBase + rl;
            const float mu = sm.mu[rl];
            const float rstd = sm.rs[rl];
#pragma unroll
            for (int nt = 0; nt < 8; ++nt) {
                const int n = w * 64 + nt * 8 + 2 * kq;
                const float2 g2 = *(const float2*)&gamma[n];
                const float2 b2 = *(const float2*)&beta[n];
                float2 o;
                o.x = (c[mt][nt][half * 2 + 0] - mu) * rstd * g2.x + b2.x;
                o.y = (c[mt][nt][half * 2 + 1] - mu) * rstd * g2.y + b2.y;
                *(float2*)&out[(size_t)m * Uu + n] = o;
            }
        }
    }
}

// ---------------------------------------------------------------------------
// Tensor-core flash attention — SINGLE __syncthreads per KV tile.
// Prefetch of tile jt+1 is issued AFTER the top barrier (all warps have
// finished iteration jt-1, the last reader of buffer cur^1, so writing it is
// race-free).  wait_group 0 at the top waits only for tile jt (issued one
// iteration earlier).  P-store hoisted right after the exp loop for ILP.
// ---------------------------------------------------------------------------
struct AttnSmem {
    uint32_t K[2][64][68];
    uint32_t V[2][64][72];
    union { uint32_t Q[64][68]; float pev[17][68]; };
    union { uint32_t P[64][68]; float pek[17][68]; };
    float qrel[64][17];
    float wsum[64][16];
};

__global__ __launch_bounds__(128) void attn_kernel(
    const float* __restrict__ pe_k, const float* __restrict__ pe_v)
{
    extern __shared__ __align__(16) char smem_raw[];
    AttnSmem& s = *reinterpret_cast<AttnSmem*>(smem_raw);

    const int tid  = threadIdx.x;
    const int lane = tid & 31;
    const int w    = tid >> 5;
    const int kq   = lane & 3;
    const int ng   = lane >> 2;
    const int it   = 15 - (int)blockIdx.x;
    const int hb   = blockIdx.y;
    const int h = hb >> 3, bidx = hb & 7;

    const float* qbase = g_qh + (size_t)hb * Tt * DH;
    const float* kbase = g_kh + (size_t)hb * Tt * DH;
    const float* vbase = g_vh + (size_t)hb * Tt * DH;

    const uint32_t kS = smem_u32(&s.K[0][0][0]);
    const uint32_t vS = smem_u32(&s.V[0][0][0]);

    auto issue_tile = [&](int buf, int jt) {
#pragma unroll
        for (int ii = 0; ii < 8; ++ii) {
            const int i = tid + ii * 128;
            const int c = i >> 4, dq = i & 15;
            cp16(kS + (((buf * 64 + c) * 68 + dq * 4) << 2),
                 &kbase[(size_t)(jt * 64 + c) * DH + dq * 4]);
            cp16(vS + (((buf * 64 + c) * 72 + dq * 4) << 2),
                 &vbase[(size_t)(jt * 64 + c) * DH + dq * 4]);
        }
        asm volatile("cp.async.commit_group;");
    };

    issue_tile(0, 0);

    for (int i = tid; i < 1024; i += 128) {
        int r = i >> 4, dq = i & 15;
        float4 a = *(const float4*)&qbase[(size_t)(it * 64 + r) * DH + dq * 4];
        s.Q[r][dq * 4 + 0] = f2tf32(a.x * 0.125f);
        s.Q[r][dq * 4 + 1] = f2tf32(a.y * 0.125f);
        s.Q[r][dq * 4 + 2] = f2tf32(a.z * 0.125f);
        s.Q[r][dq * 4 + 3] = f2tf32(a.w * 0.125f);
    }
    for (int i = tid; i < 17 * 16; i += 128) {
        int m = i / 16, dq = i % 16;
        *(float4*)&s.pek[m][dq * 4] = *(const float4*)&pe_k[m * DH + dq * 4];
    }
    for (int i = tid; i < 1024; i += 128)
        (&s.wsum[0][0])[i] = 0.f;
    __syncthreads();

    for (int i = tid; i < 64 * 17; i += 128) {
        int r = i / 17, m = i % 17;
        float acc = 0.f;
#pragma unroll 16
        for (int d = 0; d < DH; ++d)
            acc = fmaf(__uint_as_float(s.Q[r][d]), s.pek[m][d], acc);
        s.qrel[r][m] = acc;
    }
    __syncthreads();

    const int rl0 = w * 16 + ng;
    const float qrel0_0 = s.qrel[rl0][0];
    const float qrel0_1 = s.qrel[rl0 + 8][0];

    float o[8][4] = {};
    float mrow[2] = {-1e30f, -1e30f};
    float lrow[2] = {};

    for (int jt = 0; jt <= it; ++jt) {
        const int cur = jt & 1;
        // Tile jt was issued one iteration ago: wait for it, then barrier
        // (visibility for all threads' copies + all warps finished jt-1).
        asm volatile("cp.async.wait_group 0;");
        __syncthreads();
        // Prefetch jt+1 into cur^1 — safe: last reader of cur^1 was iter jt-1.
        if (jt < it) issue_tile(cur ^ 1, jt + 1);

        // ---- S = (Q/8) @ K^T ----
        float sc[8][4] = {};
#pragma unroll
        for (int ks = 0; ks < 8; ++ks) {
            const int k0 = ks * 8 + kq;
            uint32_t a[4];
            a[0] = s.Q[rl0][k0];
            a[1] = s.Q[rl0 + 8][k0];
            a[2] = s.Q[rl0][k0 + 4];
            a[3] = s.Q[rl0 + 8][k0 + 4];
#pragma unroll
            for (int nt = 0; nt < 8; ++nt) {
                uint32_t b[2];
                b[0] = s.K[cur][nt * 8 + ng][k0];
                b[1] = s.K[cur][nt * 8 + ng][k0 + 4];
                mma_tf32(sc[nt], a, b);
            }
        }

        const bool near = (jt >= it - 1);
        if (near) {
#pragma unroll
            for (int nt = 0; nt < 8; ++nt) {
#pragma unroll
                for (int ci = 0; ci < 4; ++ci) {
                    const int row_l = rl0 + ((ci >> 1) << 3);
                    const int tg = it * 64 + row_l;
                    const int sg = jt * 64 + nt * 8 + 2 * kq + (ci & 1);
                    const int delta = sg - tg;
                    if (delta > 0) sc[nt][ci] = -1e30f;
                    else {
                        int mi = delta + 16; if (mi < 0) mi = 0;
                        sc[nt][ci] += s.qrel[row_l][mi];
                    }
                }
            }
        } else {
#pragma unroll
            for (int nt = 0; nt < 8; ++nt) {
                sc[nt][0] += qrel0_0;
                sc[nt][1] += qrel0_0;
                sc[nt][2] += qrel0_1;
                sc[nt][3] += qrel0_1;
            }
        }

        // ---- online softmax ----
        float mt0 = -1e30f, mt1 = -1e30f;
#pragma unroll
        for (int nt = 0; nt < 8; ++nt) {
            mt0 = fmaxf(mt0, fmaxf(sc[nt][0], sc[nt][1]));
            mt1 = fmaxf(mt1, fmaxf(sc[nt][2], sc[nt][3]));
        }
        mt0 = fmaxf(mt0, __shfl_xor_sync(0xffffffffu, mt0, 1));
        mt0 = fmaxf(mt0, __shfl_xor_sync(0xffffffffu, mt0, 2));
        mt1 = fmaxf(mt1, __shfl_xor_sync(0xffffffffu, mt1, 1));
        mt1 = fmaxf(mt1, __shfl_xor_sync(0xffffffffu, mt1, 2));

        const float mnew0 = fmaxf(mrow[0], mt0);
        const float mnew1 = fmaxf(mrow[1], mt1);
        const float alpha0 = __expf(mrow[0] - mnew0);
        const float alpha1 = __expf(mrow[1] - mnew1);
        mrow[0] = mnew0; mrow[1] = mnew1;

#pragma unroll
        for (int nt = 0; nt < 8; ++nt) {
            sc[nt][0] = __expf(sc[nt][0] - mnew0);
            sc[nt][1] = __expf(sc[nt][1] - mnew0);
            sc[nt][2] = __expf(sc[nt][2] - mnew1);
            sc[nt][3] = __expf(sc[nt][3] - mnew1);
        }

        // ---- P -> smem early (overlaps with reductions below) ----
#pragma unroll
        for (int nt = 0; nt < 8; ++nt) {
            const int c0 = nt * 8 + 2 * kq;
            s.P[rl0][c0]         = __float_as_uint(sc[nt][0]);
            s.P[rl0][c0 + 1]     = __float_as_uint(sc[nt][1]);
            s.P[rl0 + 8][c0]     = __float_as_uint(sc[nt][2]);
            s.P[rl0 + 8][c0 + 1] = __float_as_uint(sc[nt][3]);
        }

        float ps0 = 0.f, ps1 = 0.f;
#pragma unroll
        for (int nt = 0; nt < 8; ++nt) {
            ps0 += sc[nt][0] + sc[nt][1];
            ps1 += sc[nt][2] + sc[nt][3];
        }
        ps0 += __shfl_xor_sync(0xffffffffu, ps0, 1);
        ps0 += __shfl_xor_sync(0xffffffffu, ps0, 2);
        ps1 += __shfl_xor_sync(0xffffffffu, ps1, 1);
        ps1 += __shfl_xor_sync(0xffffffffu, ps1, 2);
        lrow[0] = lrow[0] * alpha0 + ps0;
        lrow[1] = lrow[1] * alpha1 + ps1;

#pragma unroll
        for (int nt = 0; nt < 8; ++nt) {
            o[nt][0] *= alpha0; o[nt][1] *= alpha0;
            o[nt][2] *= alpha1; o[nt][3] *= alpha1;
        }

        // ---- wsum bookkeeping (warp-private rows) ----
#pragma unroll
        for (int j = 0; j < 4; ++j) {
            s.wsum[rl0][kq * 4 + j]     *= alpha0;
            s.wsum[rl0 + 8][kq * 4 + j] *= alpha1;
        }
        __syncwarp();
        if (near) {
#pragma unroll
            for (int nt = 0; nt < 8; ++nt) {
#pragma unroll
                for (int ci = 0; ci < 4; ++ci) {
                    const int row_l = rl0 + ((ci >> 1) << 3);
                    const int delta = (jt * 64 + nt * 8 + 2 * kq + (ci & 1)) - (it * 64 + row_l);
                    if (delta >= -15 && delta <= 0)
                        s.wsum[row_l][delta + 15] += sc[nt][ci];
                }
            }
        }
        __syncwarp();

        // ---- O += P @ V ----
#pragma unroll
        for (int ks = 0; ks < 8; ++ks) {
            const int k0 = ks * 8 + kq;
            uint32_t a[4];
            a[0] = s.P[rl0][k0];
            a[1] = s.P[rl0 + 8][k0];
            a[2] = s.P[rl0][k0 + 4];
            a[3] = s.P[rl0 + 8][k0 + 4];
#pragma unroll
            for (int nt = 0; nt < 8; ++nt) {
                uint32_t b[2];
                b[0] = s.V[cur][k0][nt * 8 + ng];
                b[1] = s.V[cur][k0 + 4][nt * 8 + ng];
                mma_tf32(o[nt], a, b);
            }
        }
        // no bottom barrier: next iteration's top barrier protects buffers
    }

    __syncthreads();   // all warps done with mainloop before pev overlays Q
    for (int i = tid; i < 17 * 16; i += 128) {
        int m = i / 16, dq = i % 16;
        *(float4*)&s.pev[m][dq * 4] = *(const float4*)&pe_v[m * DH + dq * 4];
    }
    __syncthreads();

#pragma unroll
    for (int half = 0; half < 2; ++half) {
        const int rl = rl0 + 8 * half;
        const int tg = it * 64 + rl;
        const float l = lrow[half];
        float wm[16], sumw = 0.f;
#pragma unroll
        for (int m = 0; m < 16; ++m) { wm[m] = s.wsum[rl][m]; sumw += wm[m]; }
        const float w0 = l - sumw;
        const float inv = 1.f / l;
#pragma unroll
        for (int nt = 0; nt < 8; ++nt) {
            const int d0 = nt * 8 + 2 * kq;
            float acc0 = o[nt][half * 2 + 0] + w0 * s.pev[0][d0];
            float acc1 = o[nt][half * 2 + 1] + w0 * s.pev[0][d0 + 1];
#pragma unroll
            for (int m = 1; m <= 16; ++m) {
                acc0 = fmaf(wm[m - 1], s.pev[m][d0], acc0);
                acc1 = fmaf(wm[m - 1], s.pev[m][d0 + 1], acc1);
            }
            float2 ov = make_float2(acc0 * inv, acc1 * inv);
            *(float2*)&g_att[((size_t)(bidx * Tt) + tg) * Uu + h * DH + d0] = ov;
        }
    }
}

// ---------------------------------------------------------------------------
extern "C" void kernel_launch(void* const* d_in, const int* in_sizes, int n_in,
                              void* d_out, int out_size) {
    (void)n_in; (void)out_size;

    int iq, ik, iv, iWq, ibq, iWk, ibk, iWv, ibv, iWo, ibo, ig, ibe, ipk, ipv;
    if (in_sizes[0] == Bb * Tt * Uu) {
        iq = 0; ik = 1; iv = 2; iWq = 3; ibq = 4; iWk = 5; ibk = 6;
        iWv = 7; ibv = 8; iWo = 9; ibo = 10; ig = 11; ibe = 12; ipk = 13; ipv = 14;
    } else if (in_sizes[0] == Uu * Uu) {
        iWk = 0; iWo = 1; iWq = 2; iWv = 3; ibe = 4; ibk = 5; ibo = 6;
        ibq = 7; ibv = 8; ig = 9; ik = 10; ipk = 11; ipv = 12; iq = 13; iv = 14;
    } else {
        ibe = 0; ibk = 1; ibo = 2; ibq = 3; ibv = 4; ig = 5; ik = 6;
        ipk = 7; ipv = 8; iq = 9; iv = 10; iWk = 11; iWo = 12; iWq = 13; iWv = 14;
    }

    const float* q    = (const float*)d_in[iq];
    const float* k    = (const float*)d_in[ik];
    const float* v    = (const float*)d_in[iv];
    const float* Wq   = (const float*)d_in[iWq];
    const float* bq   = (const float*)d_in[ibq];
    const float* Wk   = (const float*)d_in[iWk];
    const float* bk   = (const float*)d_in[ibk];
    const float* Wv   = (const float*)d_in[iWv];
    const float* bv   = (const float*)d_in[ibv];
    const float* Wo   = (const float*)d_in[iWo];
    const float* bo   = (const float*)d_in[ibo];
    const float* gamma= (const float*)d_in[ig];
    const float* beta = (const float*)d_in[ibe];
    const float* pek  = (const float*)d_in[ipk];
    const float* pev  = (const float*)d_in[ipv];
    float* out = (float*)d_out;

    cudaFuncSetAttribute(attn_kernel, cudaFuncAttributeMaxDynamicSharedMemorySize,
                         (int)sizeof(AttnSmem));
    cudaFuncSetAttribute(proj_gemm, cudaFuncAttributeMaxDynamicSharedMemorySize,
                         (int)sizeof(ProjSmem));
    cudaFuncSetAttribute(oproj_ln, cudaFuncAttributeMaxDynamicSharedMemorySize,
                         (int)sizeof(OProjSmem));

    // Q/K/V projections (one launch, z = 0/1/2)
    proj_gemm<<<dim3(4, 64, 3), 256, sizeof(ProjSmem)>>>(
        q, k, v, Wq, Wk, Wv, bq, bk, bv);

    attn_kernel<<<dim3(16, 64), 128, sizeof(AttnSmem)>>>(pek, pev);

    // Fused output projection + residual + LayerNorm -> final output
    oproj_ln<<<128, 256, sizeof(OProjSmem)>>>(Wo, bo, q, gamma, beta, out);
}

// round 13
// speedup vs baseline: 1.4636x; 1.3208x over previous
#include <cuda_runtime.h>
#include <cuda_fp16.h>
#include <math.h>
#include <stdint.h>

// Problem constants
static constexpr int Bb  = 8;
static constexpr int Tt  = 1024;
static constexpr int Uu  = 512;
static constexpr int DH  = 64;
static constexpr int HB  = 64;           // H*B
static constexpr int MR  = Bb * Tt;      // 8192 rows

// Scratch (device globals)
__device__ __half g_a16[3][(size_t)MR * Uu];     // q,k,v inputs fp16
__device__ __half g_wt16[4][(size_t)Uu * Uu];    // W^T (n-major, k contiguous) fp16
__device__ __half g_qh16[(size_t)HB * Tt * DH];  // head-split, pre-scaled 1/8
__device__ __half g_kh16[(size_t)HB * Tt * DH];  // head-split [hb][t][d]
__device__ __half g_vt16[(size_t)HB * DH * Tt];  // head-split TRANSPOSED [hb][d][t]
__device__ __half g_att16[(size_t)MR * Uu];      // attention out, merged

// ---------------------------------------------------------------------------
// Helpers
// ---------------------------------------------------------------------------
__device__ __forceinline__ void mma_f16(float c[4], const uint32_t a[4], const uint32_t b[2]) {
    asm volatile(
        "mma.sync.aligned.m16n8k16.row.col.f32.f16.f16.f32 "
        "{%0,%1,%2,%3}, {%4,%5,%6,%7}, {%8,%9}, {%0,%1,%2,%3};"
        : "+f"(c[0]), "+f"(c[1]), "+f"(c[2]), "+f"(c[3])
        : "r"(a[0]), "r"(a[1]), "r"(a[2]), "r"(a[3]), "r"(b[0]), "r"(b[1]));
}

__device__ __forceinline__ void cp16(uint32_t saddr, const void* gptr) {
    asm volatile("cp.async.cg.shared.global [%0], [%1], 16;" :: "r"(saddr), "l"(gptr));
}

__device__ __forceinline__ uint32_t smem_u32(const void* p) {
    uint32_t a;
    asm("{ .reg .u64 t; cvta.to.shared.u64 t, %1; cvt.u32.u64 %0, t; }" : "=r"(a) : "l"(p));
    return a;
}

// ---------------------------------------------------------------------------
// Input conversion: q/k/v fp32 -> fp16 (grid.y = z)
// ---------------------------------------------------------------------------
__global__ __launch_bounds__(512) void cvt_in(
    const float* __restrict__ q, const float* __restrict__ k, const float* __restrict__ v)
{
    const int z = blockIdx.y;
    const float* src = (z == 0) ? q : (z == 1) ? k : v;
    __half* dst = g_a16[z];
    const size_t i = (size_t)blockIdx.x * 512 + threadIdx.x;   // float4 index
    float4 a = ((const float4*)src)[i];
    __half2 h0 = __floats2half2_rn(a.x, a.y);
    __half2 h1 = __floats2half2_rn(a.z, a.w);
    *(__half2*)&dst[i * 4]     = h0;
    *(__half2*)&dst[i * 4 + 2] = h1;
}

// ---------------------------------------------------------------------------
// Weight transpose + convert: g_wt16[z][n][k] = W_z[k][n] fp16
// ---------------------------------------------------------------------------
__global__ __launch_bounds__(256) void cvt_w(
    const float* __restrict__ Wq, const float* __restrict__ Wk,
    const float* __restrict__ Wv, const float* __restrict__ Wo)
{
    __shared__ float t[32][33];
    const int z = blockIdx.z;
    const float* W = (z == 0) ? Wq : (z == 1) ? Wk : (z == 2) ? Wv : Wo;
    __half* dst = g_wt16[z];
    const int tx = threadIdx.x & 31, ty = threadIdx.x >> 5;
    const int kb = blockIdx.y * 32, nb = blockIdx.x * 32;
#pragma unroll
    for (int i = 0; i < 4; ++i)
        t[ty + i * 8][tx] = W[(size_t)(kb + ty + i * 8) * Uu + nb + tx];
    __syncthreads();
#pragma unroll
    for (int i = 0; i < 4; ++i)
        dst[(size_t)(nb + ty + i * 8) * Uu + kb + tx] = __float2half_rn(t[tx][ty + i * 8]);
}

// ---------------------------------------------------------------------------
// FP16 QKV projection GEMM: 128x128 tile, BK=32, 3-stage cp.async, 256 thr
// (8 warps 2x4, warp tile 64x32).  mma m16n8k16.  z selects q/k/v.
// Outputs fp16: z=0 -> g_qh16 (x0.125), z=1 -> g_kh16, z=2 -> g_vt16 (transposed)
// smem words hold half2 pairs; stride 20 words -> conflict-free fragment LDS.
// ---------------------------------------------------------------------------
struct ProjSmem {
    uint32_t As[3][128][20];   // 30720 B  [r][k-pair]
    uint32_t Bs[3][128][20];   // 30720 B  [n][k-pair]
};

__global__ __launch_bounds__(256, 2) void proj_gemm(
    const float* __restrict__ bq, const float* __restrict__ bk, const float* __restrict__ bv)
{
    extern __shared__ __align__(1024) char smem_raw[];
    ProjSmem& sm = *reinterpret_cast<ProjSmem*>(smem_raw);

    const int z = blockIdx.z;
    const __half* A  = g_a16[z];
    const __half* Wt = g_wt16[z];
    const float* bias = (z == 0) ? bq : (z == 1) ? bk : bv;

    const int tid  = threadIdx.x;
    const int lane = tid & 31;
    const int wid  = tid >> 5;
    const int wm   = wid >> 2;            // 0..1
    const int wn   = wid & 3;             // 0..3
    const int kq   = lane & 3;
    const int ng   = lane >> 2;
    const int rowBase = blockIdx.y * 128;
    const int nBase   = blockIdx.x * 128;

    const uint32_t aS = smem_u32(&sm.As[0][0][0]);
    const uint32_t bS = smem_u32(&sm.Bs[0][0][0]);

    auto issue = [&](int s, int kt) {
        const int kb = kt * 32;
#pragma unroll
        for (int ii = 0; ii < 2; ++ii) {
            const int idx = tid + ii * 256;       // A: 128 rows x 4 chunks(8 halves)
            const int r = idx >> 2, c4 = idx & 3;
            cp16(aS + (((s * 128 + r) * 20 + c4 * 4) << 2),
                 &A[(size_t)(rowBase + r) * Uu + kb + c4 * 8]);
        }
#pragma unroll
        for (int ii = 0; ii < 2; ++ii) {
            const int idx = tid + ii * 256;       // B: 128 n-rows x 4 chunks
            const int n = idx >> 2, c4 = idx & 3;
            cp16(bS + (((s * 128 + n) * 20 + c4 * 4) << 2),
                 &Wt[(size_t)(nBase + n) * Uu + kb + c4 * 8]);
        }
        asm volatile("cp.async.commit_group;");
    };

    constexpr int NIT = Uu / 32;   // 16
    issue(0, 0);
    issue(1, 1);

    const int r0 = wm * 64 + ng;
    const int n0 = wn * 32 + ng;

    float c[4][4][4] = {};

    for (int kb = 0; kb < NIT; ++kb) {
        const int cur = kb % 3;
        if (kb + 1 < NIT) asm volatile("cp.async.wait_group 1;");
        else              asm volatile("cp.async.wait_group 0;");
        __syncthreads();

#pragma unroll
        for (int ks = 0; ks < 2; ++ks) {
            const int j0 = ks * 8 + kq;
            uint32_t a[4][4];
#pragma unroll
            for (int mt = 0; mt < 4; ++mt) {
                const int rr = r0 + mt * 16;
                a[mt][0] = sm.As[cur][rr][j0];
                a[mt][1] = sm.As[cur][rr + 8][j0];
                a[mt][2] = sm.As[cur][rr][j0 + 4];
                a[mt][3] = sm.As[cur][rr + 8][j0 + 4];
            }
#pragma unroll
            for (int nt = 0; nt < 4; ++nt) {
                uint32_t b[2];
                b[0] = sm.Bs[cur][n0 + nt * 8][j0];
                b[1] = sm.Bs[cur][n0 + nt * 8][j0 + 4];
#pragma unroll
                for (int mt = 0; mt < 4; ++mt)
                    mma_f16(c[mt][nt], a[mt], b);
            }
        }

        if (kb + 2 < NIT) issue((kb + 2) % 3, kb + 2);
    }

    // Epilogue: bias + relu, fp16 head-split outputs
    const float scale = (z == 0) ? 0.125f : 1.0f;
#pragma unroll
    for (int mt = 0; mt < 4; ++mt) {
        const int rbase = rowBase + wm * 64 + mt * 16 + ng;
#pragma unroll
        for (int nt = 0; nt < 4; ++nt) {
            const int n = nBase + wn * 32 + nt * 8 + 2 * kq;
            const float2 bi = *(const float2*)&bias[n];
            const int hh = n >> 6, d = n & 63;
#pragma unroll
            for (int half_ = 0; half_ < 2; ++half_) {
                const int m = rbase + half_ * 8;
                const int bidx = m >> 10, t = m & 1023;
                float ox = fmaxf(c[mt][nt][half_ * 2 + 0] + bi.x, 0.f) * scale;
                float oy = fmaxf(c[mt][nt][half_ * 2 + 1] + bi.y, 0.f) * scale;
                if (z < 2) {
                    __half* dst = (z == 0) ? g_qh16 : g_kh16;
                    *(__half2*)&dst[((size_t)(hh * 8 + bidx) * Tt + t) * DH + d] =
                        __floats2half2_rn(ox, oy);
                } else {
                    g_vt16[((size_t)(hh * 8 + bidx) * DH + d) * Tt + t]     = __float2half_rn(ox);
                    g_vt16[((size_t)(hh * 8 + bidx) * DH + d + 1) * Tt + t] = __float2half_rn(oy);
                }
            }
        }
    }
}

// ---------------------------------------------------------------------------
// FP16 flash attention.  Q pre-scaled 1/8 in fp16; K [t][d]; V^T [d][t].
// m16n8k16: 4 k-steps per 64-dim instead of 8.  Single barrier per tile.
// smem strides 36 words: fragment LDS banks = 4*ng + kq -> conflict-free.
// ---------------------------------------------------------------------------
struct AttnSmem {
    uint32_t K[2][64][36];   // [c][d-pair]
    uint32_t V[2][64][36];   // V^T: [d][c-pair]
    union { uint32_t Q[64][36]; float pev[17][68]; };
    union { uint32_t P[64][36]; float pek[17][68]; };
    float qrel[64][17];
    float wsum[64][16];
};

__global__ __launch_bounds__(128) void attn_kernel(
    const float* __restrict__ pe_k, const float* __restrict__ pe_v)
{
    extern __shared__ __align__(1024) char smem_raw[];
    AttnSmem& s = *reinterpret_cast<AttnSmem*>(smem_raw);

    const int tid  = threadIdx.x;
    const int lane = tid & 31;
    const int w    = tid >> 5;
    const int kq   = lane & 3;
    const int ng   = lane >> 2;
    const int it   = 15 - (int)blockIdx.x;
    const int hb   = blockIdx.y;
    const int hh = hb >> 3, bidx = hb & 7;

    const __half* qbase = g_qh16 + (size_t)hb * Tt * DH;
    const __half* kbase = g_kh16 + (size_t)hb * Tt * DH;
    const __half* vbase = g_vt16 + (size_t)hb * DH * Tt;

    const uint32_t kS = smem_u32(&s.K[0][0][0]);
    const uint32_t vS = smem_u32(&s.V[0][0][0]);
    const uint32_t qS = smem_u32(&s.Q[0][0]);

    // K tile: 64 rows x 8 chunks ; V^T tile: 64 d-rows x 8 chunks (t-slice)
    auto issue_tile = [&](int buf, int jt) {
#pragma unroll
        for (int ii = 0; ii < 4; ++ii) {
            const int i = tid + ii * 128;
            const int r = i >> 3, c8 = i & 7;
            cp16(kS + (((buf * 64 + r) * 36 + c8 * 4) << 2),
                 &kbase[(size_t)(jt * 64 + r) * DH + c8 * 8]);
        }
#pragma unroll
        for (int ii = 0; ii < 4; ++ii) {
            const int i = tid + ii * 128;
            const int d = i >> 3, c8 = i & 7;
            cp16(vS + (((buf * 64 + d) * 36 + c8 * 4) << 2),
                 &vbase[(size_t)d * Tt + jt * 64 + c8 * 8]);
        }
        asm volatile("cp.async.commit_group;");
    };

    issue_tile(0, 0);
    // Q tile (group 2)
#pragma unroll
    for (int ii = 0; ii < 4; ++ii) {
        const int i = tid + ii * 128;
        const int r = i >> 3, c8 = i & 7;
        cp16(qS + ((r * 36 + c8 * 4) << 2),
             &qbase[(size_t)(it * 64 + r) * DH + c8 * 8]);
    }
    asm volatile("cp.async.commit_group;");

    // pek (overlay on P), wsum zero
    for (int i = tid; i < 17 * 16; i += 128) {
        int m = i / 16, dq = i % 16;
        *(float4*)&s.pek[m][dq * 4] = *(const float4*)&pe_k[m * DH + dq * 4];
    }
    for (int i = tid; i < 1024; i += 128)
        (&s.wsum[0][0])[i] = 0.f;

    asm volatile("cp.async.wait_group 0;");   // Q + tile0 both complete
    __syncthreads();

    // qrel[r][m] = Qscaled . pe_k[m]
    for (int i = tid; i < 64 * 17; i += 128) {
        int r = i / 17, m = i % 17;
        float acc = 0.f;
#pragma unroll
        for (int j = 0; j < 32; ++j) {
            float2 f = __half22float2(*(const __half2*)&s.Q[r][j]);
            acc = fmaf(f.x, s.pek[m][2 * j], acc);
            acc = fmaf(f.y, s.pek[m][2 * j + 1], acc);
        }
        s.qrel[r][m] = acc;
    }
    __syncthreads();   // pek (P region) free after this

    const int rl0 = w * 16 + ng;
    const float qrel0_0 = s.qrel[rl0][0];
    const float qrel0_1 = s.qrel[rl0 + 8][0];

    float o[8][4] = {};
    float mrow[2] = {-1e30f, -1e30f};
    float lrow[2] = {};

    for (int jt = 0; jt <= it; ++jt) {
        const int cur = jt & 1;
        asm volatile("cp.async.wait_group 0;");
        __syncthreads();
        if (jt < it) issue_tile(cur ^ 1, jt + 1);

        // ---- S = Qs @ K^T ----
        float sc[8][4] = {};
#pragma unroll
        for (int ks = 0; ks < 4; ++ks) {
            const int j0 = ks * 8 + kq;
            uint32_t a[4];
            a[0] = s.Q[rl0][j0];
            a[1] = s.Q[rl0 + 8][j0];
            a[2] = s.Q[rl0][j0 + 4];
            a[3] = s.Q[rl0 + 8][j0 + 4];
#pragma unroll
            for (int nt = 0; nt < 8; ++nt) {
                uint32_t b[2];
                b[0] = s.K[cur][nt * 8 + ng][j0];
                b[1] = s.K[cur][nt * 8 + ng][j0 + 4];
                mma_f16(sc[nt], a, b);
            }
        }

        const bool near = (jt >= it - 1);
        if (near) {
#pragma unroll
            for (int nt = 0; nt < 8; ++nt) {
#pragma unroll
                for (int ci = 0; ci < 4; ++ci) {
                    const int row_l = rl0 + ((ci >> 1) << 3);
                    const int tg = it * 64 + row_l;
                    const int sg = jt * 64 + nt * 8 + 2 * kq + (ci & 1);
                    const int delta = sg - tg;
                    if (delta > 0) sc[nt][ci] = -1e30f;
                    else {
                        int mi = delta + 16; if (mi < 0) mi = 0;
                        sc[nt][ci] += s.qrel[row_l][mi];
                    }
                }
            }
        } else {
#pragma unroll
            for (int nt = 0; nt < 8; ++nt) {
                sc[nt][0] += qrel0_0;
                sc[nt][1] += qrel0_0;
                sc[nt][2] += qrel0_1;
                sc[nt][3] += qrel0_1;
            }
        }

        // ---- online softmax ----
        float mt0 = -1e30f, mt1 = -1e30f;
#pragma unroll
        for (int nt = 0; nt < 8; ++nt) {
            mt0 = fmaxf(mt0, fmaxf(sc[nt][0], sc[nt][1]));
            mt1 = fmaxf(mt1, fmaxf(sc[nt][2], sc[nt][3]));
        }
        mt0 = fmaxf(mt0, __shfl_xor_sync(0xffffffffu, mt0, 1));
        mt0 = fmaxf(mt0, __shfl_xor_sync(0xffffffffu, mt0, 2));
        mt1 = fmaxf(mt1, __shfl_xor_sync(0xffffffffu, mt1, 1));
        mt1 = fmaxf(mt1, __shfl_xor_sync(0xffffffffu, mt1, 2));

        const float mnew0 = fmaxf(mrow[0], mt0);
        const float mnew1 = fmaxf(mrow[1], mt1);
        const float alpha0 = __expf(mrow[0] - mnew0);
        const float alpha1 = __expf(mrow[1] - mnew1);
        mrow[0] = mnew0; mrow[1] = mnew1;

#pragma unroll
        for (int nt = 0; nt < 8; ++nt) {
            sc[nt][0] = __expf(sc[nt][0] - mnew0);
            sc[nt][1] = __expf(sc[nt][1] - mnew0);
            sc[nt][2] = __expf(sc[nt][2] - mnew1);
            sc[nt][3] = __expf(sc[nt][3] - mnew1);
        }

        // ---- P -> smem as half2 (early, overlaps reductions) ----
#pragma unroll
        for (int nt = 0; nt < 8; ++nt) {
            const int j = nt * 4 + kq;
            *(__half2*)&s.P[rl0][j]     = __floats2half2_rn(sc[nt][0], sc[nt][1]);
            *(__half2*)&s.P[rl0 + 8][j] = __floats2half2_rn(sc[nt][2], sc[nt][3]);
        }

        float ps0 = 0.f, ps1 = 0.f;
#pragma unroll
        for (int nt = 0; nt < 8; ++nt) {
            ps0 += sc[nt][0] + sc[nt][1];
            ps1 += sc[nt][2] + sc[nt][3];
        }
        ps0 += __shfl_xor_sync(0xffffffffu, ps0, 1);
        ps0 += __shfl_xor_sync(0xffffffffu, ps0, 2);
        ps1 += __shfl_xor_sync(0xffffffffu, ps1, 1);
        ps1 += __shfl_xor_sync(0xffffffffu, ps1, 2);
        lrow[0] = lrow[0] * alpha0 + ps0;
        lrow[1] = lrow[1] * alpha1 + ps1;

#pragma unroll
        for (int nt = 0; nt < 8; ++nt) {
            o[nt][0] *= alpha0; o[nt][1] *= alpha0;
            o[nt][2] *= alpha1; o[nt][3] *= alpha1;
        }

        // ---- wsum bookkeeping ----
#pragma unroll
        for (int j = 0; j < 4; ++j) {
            s.wsum[rl0][kq * 4 + j]     *= alpha0;
            s.wsum[rl0 + 8][kq * 4 + j] *= alpha1;
        }
        __syncwarp();
        if (near) {
#pragma unroll
            for (int nt = 0; nt < 8; ++nt) {
#pragma unroll
                for (int ci = 0; ci < 4; ++ci) {
                    const int row_l = rl0 + ((ci >> 1) << 3);
                    const int delta = (jt * 64 + nt * 8 + 2 * kq + (ci & 1)) - (it * 64 + row_l);
                    if (delta >= -15 && delta <= 0)
                        s.wsum[row_l][delta + 15] += sc[nt][ci];
                }
            }
        }
        __syncwarp();

        // ---- O += P @ V (B from V^T, pairs contiguous) ----
#pragma unroll
        for (int ks = 0; ks < 4; ++ks) {
            const int j0 = ks * 8 + kq;
            uint32_t a[4];
            a[0] = s.P[rl0][j0];
            a[1] = s.P[rl0 + 8][j0];
            a[2] = s.P[rl0][j0 + 4];
            a[3] = s.P[rl0 + 8][j0 + 4];
#pragma unroll
            for (int nt = 0; nt < 8; ++nt) {
                uint32_t b[2];
                b[0] = s.V[cur][nt * 8 + ng][j0];
                b[1] = s.V[cur][nt * 8 + ng][j0 + 4];
                mma_f16(o[nt], a, b);
            }
        }
    }

    __syncthreads();
    for (int i = tid; i < 17 * 16; i += 128) {
        int m = i / 16, dq = i % 16;
        *(float4*)&s.pev[m][dq * 4] = *(const float4*)&pe_v[m * DH + dq * 4];
    }
    __syncthreads();

#pragma unroll
    for (int half_ = 0; half_ < 2; ++half_) {
        const int rl = rl0 + 8 * half_;
        const int tg = it * 64 + rl;
        const float l = lrow[half_];
        float wm[16], sumw = 0.f;
#pragma unroll
        for (int m = 0; m < 16; ++m) { wm[m] = s.wsum[rl][m]; sumw += wm[m]; }
        const float w0 = l - sumw;
        const float inv = 1.f / l;
#pragma unroll
        for (int nt = 0; nt < 8; ++nt) {
            const int d0 = nt * 8 + 2 * kq;
            float acc0 = o[nt][half_ * 2 + 0] + w0 * s.pev[0][d0];
            float acc1 = o[nt][half_ * 2 + 1] + w0 * s.pev[0][d0 + 1];
#pragma unroll
            for (int m = 1; m <= 16; ++m) {
                acc0 = fmaf(wm[m - 1], s.pev[m][d0], acc0);
                acc1 = fmaf(wm[m - 1], s.pev[m][d0 + 1], acc1);
            }
            *(__half2*)&g_att16[((size_t)(bidx * Tt) + tg) * Uu + hh * DH + d0] =
                __floats2half2_rn(acc0 * inv, acc1 * inv);
        }
    }
}

// ---------------------------------------------------------------------------
// Fused out-projection + residual + LayerNorm, fp16 mma, BK=16, 4 stages.
// One block = 64 rows x 512 cols.  A = g_att16, B = g_wt16[3] (Wo^T).
// ---------------------------------------------------------------------------
struct OProjSmem {
    uint32_t As[4][64][12];     // 12288 B [r][k-pair]
    uint32_t Bs[4][512][12];    // 98304 B [n][k-pair]
    float part[2][8][64];       // 4096 B
    float mu[64];
    float rs[64];
};

__global__ __launch_bounds__(256) void oproj_ln(
    const float* __restrict__ bo,
    const float* __restrict__ res,
    const float* __restrict__ gamma, const float* __restrict__ beta,
    float* __restrict__ out)
{
    extern __shared__ __align__(1024) char smem_raw[];
    OProjSmem& sm = *reinterpret_cast<OProjSmem*>(smem_raw);

    const int tid  = threadIdx.x;
    const int lane = tid & 31;
    const int w    = tid >> 5;
    const int kq   = lane & 3;
    const int ng   = lane >> 2;
    const int rowBase = blockIdx.x * 64;

    const __half* Wt = g_wt16[3];
    const uint32_t aS = smem_u32(&sm.As[0][0][0]);
    const uint32_t bS = smem_u32(&sm.Bs[0][0][0]);

    auto issue = [&](int s, int kt) {
        const int kb = kt * 16;
        if (tid < 128) {                     // A: 64 rows x 2 chunks
            const int r = tid >> 1, c2 = tid & 1;
            cp16(aS + (((s * 64 + r) * 12 + c2 * 4) << 2),
                 &g_att16[(size_t)(rowBase + r) * Uu + kb + c2 * 8]);
        }
#pragma unroll
        for (int ii = 0; ii < 4; ++ii) {     // B: 512 n-rows x 2 chunks
            const int idx = tid + ii * 256;
            const int n = idx >> 1, c2 = idx & 1;
            cp16(bS + (((s * 512 + n) * 12 + c2 * 4) << 2),
                 &Wt[(size_t)n * Uu + kb + c2 * 8]);
        }
        asm volatile("cp.async.commit_group;");
    };

    constexpr int NIT = Uu / 16;   // 32
    issue(0, 0);
    issue(1, 1);
    issue(2, 2);

    float c[4][8][4] = {};

    for (int kb = 0; kb < NIT; ++kb) {
        const int cur = kb & 3;
        if      (kb + 2 < NIT) asm volatile("cp.async.wait_group 2;");
        else if (kb + 1 < NIT) asm volatile("cp.async.wait_group 1;");
        else                   asm volatile("cp.async.wait_group 0;");
        __syncthreads();

        uint32_t a[4][4];
#pragma unroll
        for (int mt = 0; mt < 4; ++mt) {
            const int r0 = mt * 16 + ng;
            a[mt][0] = sm.As[cur][r0][kq];
            a[mt][1] = sm.As[cur][r0 + 8][kq];
            a[mt][2] = sm.As[cur][r0][kq + 4];
            a[mt][3] = sm.As[cur][r0 + 8][kq + 4];
        }
#pragma unroll
        for (int nt = 0; nt < 8; ++nt) {
            uint32_t b[2];
            const int n0 = w * 64 + nt * 8 + ng;
            b[0] = sm.Bs[cur][n0][kq];
            b[1] = sm.Bs[cur][n0][kq + 4];
#pragma unroll
            for (int mt = 0; mt < 4; ++mt)
                mma_f16(c[mt][nt], a[mt], b);
        }

        if (kb + 3 < NIT) issue((kb + 3) & 3, kb + 3);
    }

    // ---- bias + relu + residual; per-row partial stats ----
    float psum[8] = {}, psq[8] = {};
#pragma unroll
    for (int mt = 0; mt < 4; ++mt) {
#pragma unroll
        for (int half_ = 0; half_ < 2; ++half_) {
            const int m = rowBase + mt * 16 + ng + half_ * 8;
            const int slot = mt * 2 + half_;
#pragma unroll
            for (int nt = 0; nt < 8; ++nt) {
                const int n = w * 64 + nt * 8 + 2 * kq;
                const float2 bi = *(const float2*)&bo[n];
                const float2 r2 = *(const float2*)&res[(size_t)m * Uu + n];
                float vx = fmaxf(c[mt][nt][half_ * 2 + 0] + bi.x, 0.f) + r2.x;
                float vy = fmaxf(c[mt][nt][half_ * 2 + 1] + bi.y, 0.f) + r2.y;
                c[mt][nt][half_ * 2 + 0] = vx;
                c[mt][nt][half_ * 2 + 1] = vy;
                psum[slot] += vx + vy;
                psq[slot]  += vx * vx + vy * vy;
            }
        }
    }
#pragma unroll
    for (int slot = 0; slot < 8; ++slot) {
        psum[slot] += __shfl_xor_sync(0xffffffffu, psum[slot], 1);
        psum[slot] += __shfl_xor_sync(0xffffffffu, psum[slot], 2);
        psq[slot]  += __shfl_xor_sync(0xffffffffu, psq[slot], 1);
        psq[slot]  += __shfl_xor_sync(0xffffffffu, psq[slot], 2);
    }
    if (kq == 0) {
#pragma unroll
        for (int mt = 0; mt < 4; ++mt)
#pragma unroll
            for (int half_ = 0; half_ < 2; ++half_) {
                const int rl = mt * 16 + ng + half_ * 8;
                sm.part[0][w][rl] = psum[mt * 2 + half_];
                sm.part[1][w][rl] = psq[mt * 2 + half_];
            }
    }
    __syncthreads();

    if (tid < 64) {
        float su = 0.f, sq = 0.f;
#pragma unroll
        for (int wi = 0; wi < 8; ++wi) {
            su += sm.part[0][wi][tid];
            sq += sm.part[1][wi][tid];
        }
        const float mu = su * (1.f / Uu);
        const float var = sq * (1.f / Uu) - mu * mu;
        sm.mu[tid] = mu;
        sm.rs[tid] = rsqrtf(var + 1e-3f);
    }
    __syncthreads();

#pragma unroll
    for (int mt = 0; mt < 4; ++mt) {
#pragma unroll
        for (int half_ = 0; half_ < 2; ++half_) {
            const int rl = mt * 16 + ng + half_ * 8;
            const int m = rowBase + rl;
            const float mu = sm.mu[rl];
            const float rstd = sm.rs[rl];
#pragma unroll
            for (int nt = 0; nt < 8; ++nt) {
                const int n = w * 64 + nt * 8 + 2 * kq;
                const float2 g2 = *(const float2*)&gamma[n];
                const float2 b2 = *(const float2*)&beta[n];
                float2 o;
                o.x = (c[mt][nt][half_ * 2 + 0] - mu) * rstd * g2.x + b2.x;
                o.y = (c[mt][nt][half_ * 2 + 1] - mu) * rstd * g2.y + b2.y;
                *(float2*)&out[(size_t)m * Uu + n] = o;
            }
        }
    }
}

// ---------------------------------------------------------------------------
extern "C" void kernel_launch(void* const* d_in, const int* in_sizes, int n_in,
                              void* d_out, int out_size) {
    (void)n_in; (void)out_size;

    int iq, ik, iv, iWq, ibq, iWk, ibk, iWv, ibv, iWo, ibo, ig, ibe, ipk, ipv;
    if (in_sizes[0] == Bb * Tt * Uu) {
        iq = 0; ik = 1; iv = 2; iWq = 3; ibq = 4; iWk = 5; ibk = 6;
        iWv = 7; ibv = 8; iWo = 9; ibo = 10; ig = 11; ibe = 12; ipk = 13; ipv = 14;
    } else if (in_sizes[0] == Uu * Uu) {
        iWk = 0; iWo = 1; iWq = 2; iWv = 3; ibe = 4; ibk = 5; ibo = 6;
        ibq = 7; ibv = 8; ig = 9; ik = 10; ipk = 11; ipv = 12; iq = 13; iv = 14;
    } else {
        ibe = 0; ibk = 1; ibo = 2; ibq = 3; ibv = 4; ig = 5; ik = 6;
        ipk = 7; ipv = 8; iq = 9; iv = 10; iWk = 11; iWo = 12; iWq = 13; iWv = 14;
    }

    const float* q    = (const float*)d_in[iq];
    const float* k    = (const float*)d_in[ik];
    const float* v    = (const float*)d_in[iv];
    const float* Wq   = (const float*)d_in[iWq];
    const float* bq   = (const float*)d_in[ibq];
    const float* Wk   = (const float*)d_in[iWk];
    const float* bk   = (const float*)d_in[ibk];
    const float* Wv   = (const float*)d_in[iWv];
    const float* bv   = (const float*)d_in[ibv];
    const float* Wo   = (const float*)d_in[iWo];
    const float* bo   = (const float*)d_in[ibo];
    const float* gamma= (const float*)d_in[ig];
    const float* beta = (const float*)d_in[ibe];
    const float* pek  = (const float*)d_in[ipk];
    const float* pev  = (const float*)d_in[ipv];
    float* out = (float*)d_out;

    cudaFuncSetAttribute(attn_kernel, cudaFuncAttributeMaxDynamicSharedMemorySize,
                         (int)sizeof(AttnSmem));
    cudaFuncSetAttribute(proj_gemm, cudaFuncAttributeMaxDynamicSharedMemorySize,
                         (int)sizeof(ProjSmem));
    cudaFuncSetAttribute(oproj_ln, cudaFuncAttributeMaxDynamicSharedMemorySize,
                         (int)sizeof(OProjSmem));

    // Convert inputs + weights to fp16 (weights transposed)
    cvt_in<<<dim3(MR * Uu / 4 / 512, 3), 512>>>(q, k, v);
    cvt_w<<<dim3(16, 16, 4), 256>>>(Wq, Wk, Wv, Wo);

    // Q/K/V projections (fp16 mma), head-split fp16 outputs
    proj_gemm<<<dim3(4, 64, 3), 256, sizeof(ProjSmem)>>>(bq, bk, bv);

    attn_kernel<<<dim3(16, 64), 128, sizeof(AttnSmem)>>>(pek, pev);

    // Fused output projection + residual + LayerNorm -> final fp32 output
    oproj_ln<<<128, 256, sizeof(OProjSmem)>>>(bo, q, gamma, beta, out);
}

// round 15
// speedup vs baseline: 1.4935x; 1.0204x over previous
#include <cuda_runtime.h>
#include <cuda_fp16.h>
#include <math.h>
#include <stdint.h>

// Problem constants
static constexpr int Bb  = 8;
static constexpr int Tt  = 1024;
static constexpr int Uu  = 512;
static constexpr int DH  = 64;
static constexpr int HB  = 64;           // H*B
static constexpr int MR  = Bb * Tt;      // 8192 rows

// Scratch (device globals)
__device__ __half g_a16[3][(size_t)MR * Uu];     // q,k,v inputs fp16
__device__ __half g_wt16[4][(size_t)Uu * Uu];    // W^T (n-major, k contiguous) fp16
__device__ __half g_qh16[(size_t)HB * Tt * DH];  // head-split, pre-scaled 1/8
__device__ __half g_kh16[(size_t)HB * Tt * DH];  // head-split [hb][t][d]
__device__ __half g_vt16[(size_t)HB * DH * Tt];  // head-split TRANSPOSED [hb][d][t]
__device__ __half g_att16[(size_t)MR * Uu];      // attention out, merged

// ---------------------------------------------------------------------------
// Helpers
// ---------------------------------------------------------------------------
__device__ __forceinline__ void mma_f16(float c[4], const uint32_t a[4], const uint32_t b[2]) {
    asm volatile(
        "mma.sync.aligned.m16n8k16.row.col.f32.f16.f16.f32 "
        "{%0,%1,%2,%3}, {%4,%5,%6,%7}, {%8,%9}, {%0,%1,%2,%3};"
        : "+f"(c[0]), "+f"(c[1]), "+f"(c[2]), "+f"(c[3])
        : "r"(a[0]), "r"(a[1]), "r"(a[2]), "r"(a[3]), "r"(b[0]), "r"(b[1]));
}

__device__ __forceinline__ void cp16(uint32_t saddr, const void* gptr) {
    asm volatile("cp.async.cg.shared.global [%0], [%1], 16;" :: "r"(saddr), "l"(gptr));
}

__device__ __forceinline__ uint32_t smem_u32(const void* p) {
    uint32_t a;
    asm("{ .reg .u64 t; cvta.to.shared.u64 t, %1; cvt.u32.u64 %0, t; }" : "=r"(a) : "l"(p));
    return a;
}

// pack two fp32 -> f16x2 in a b32 register (RN rounding, same as __floats2half2_rn)
__device__ __forceinline__ uint32_t packh2(float x, float y) {
    uint32_t r;
    asm("cvt.rn.f16x2.f32 %0, %1, %2;" : "=r"(r) : "f"(y), "f"(x));
    return r;
}

// ---------------------------------------------------------------------------
// Input conversion: q/k/v fp32 -> fp16 (grid.y = z)
// ---------------------------------------------------------------------------
__global__ __launch_bounds__(512) void cvt_in(
    const float* __restrict__ q, const float* __restrict__ k, const float* __restrict__ v)
{
    const int z = blockIdx.y;
    const float* src = (z == 0) ? q : (z == 1) ? k : v;
    __half* dst = g_a16[z];
    const size_t i = (size_t)blockIdx.x * 512 + threadIdx.x;   // float4 index
    float4 a = ((const float4*)src)[i];
    *(__half2*)&dst[i * 4]     = __floats2half2_rn(a.x, a.y);
    *(__half2*)&dst[i * 4 + 2] = __floats2half2_rn(a.z, a.w);
}

// ---------------------------------------------------------------------------
// Weight transpose + convert: g_wt16[z][n][k] = W_z[k][n] fp16
// ---------------------------------------------------------------------------
__global__ __launch_bounds__(256) void cvt_w(
    const float* __restrict__ Wq, const float* __restrict__ Wk,
    const float* __restrict__ Wv, const float* __restrict__ Wo)
{
    __shared__ float t[32][33];
    const int z = blockIdx.z;
    const float* W = (z == 0) ? Wq : (z == 1) ? Wk : (z == 2) ? Wv : Wo;
    __half* dst = g_wt16[z];
    const int tx = threadIdx.x & 31, ty = threadIdx.x >> 5;
    const int kb = blockIdx.y * 32, nb = blockIdx.x * 32;
#pragma unroll
    for (int i = 0; i < 4; ++i)
        t[ty + i * 8][tx] = W[(size_t)(kb + ty + i * 8) * Uu + nb + tx];
    __syncthreads();
#pragma unroll
    for (int i = 0; i < 4; ++i)
        dst[(size_t)(nb + ty + i * 8) * Uu + kb + tx] = __float2half_rn(t[tx][ty + i * 8]);
}

// ---------------------------------------------------------------------------
// FP16 QKV projection GEMM (r13 winner, unchanged).
// ---------------------------------------------------------------------------
struct ProjSmem {
    uint32_t As[3][128][20];   // 30720 B  [r][k-pair]
    uint32_t Bs[3][128][20];   // 30720 B  [n][k-pair]
};

__global__ __launch_bounds__(256, 2) void proj_gemm(
    const float* __restrict__ bq, const float* __restrict__ bk, const float* __restrict__ bv)
{
    extern __shared__ __align__(1024) char smem_raw[];
    ProjSmem& sm = *reinterpret_cast<ProjSmem*>(smem_raw);

    const int z = blockIdx.z;
    const __half* A  = g_a16[z];
    const __half* Wt = g_wt16[z];
    const float* bias = (z == 0) ? bq : (z == 1) ? bk : bv;

    const int tid  = threadIdx.x;
    const int lane = tid & 31;
    const int wid  = tid >> 5;
    const int wm   = wid >> 2;            // 0..1
    const int wn   = wid & 3;             // 0..3
    const int kq   = lane & 3;
    const int ng   = lane >> 2;
    const int rowBase = blockIdx.y * 128;
    const int nBase   = blockIdx.x * 128;

    const uint32_t aS = smem_u32(&sm.As[0][0][0]);
    const uint32_t bS = smem_u32(&sm.Bs[0][0][0]);

    auto issue = [&](int s, int kt) {
        const int kb = kt * 32;
#pragma unroll
        for (int ii = 0; ii < 2; ++ii) {
            const int idx = tid + ii * 256;
            const int r = idx >> 2, c4 = idx & 3;
            cp16(aS + (((s * 128 + r) * 20 + c4 * 4) << 2),
                 &A[(size_t)(rowBase + r) * Uu + kb + c4 * 8]);
        }
#pragma unroll
        for (int ii = 0; ii < 2; ++ii) {
            const int idx = tid + ii * 256;
            const int n = idx >> 2, c4 = idx & 3;
            cp16(bS + (((s * 128 + n) * 20 + c4 * 4) << 2),
                 &Wt[(size_t)(nBase + n) * Uu + kb + c4 * 8]);
        }
        asm volatile("cp.async.commit_group;");
    };

    constexpr int NIT = Uu / 32;   // 16
    issue(0, 0);
    issue(1, 1);

    const int r0 = wm * 64 + ng;
    const int n0 = wn * 32 + ng;

    float c[4][4][4] = {};

    for (int kb = 0; kb < NIT; ++kb) {
        const int cur = kb % 3;
        if (kb + 1 < NIT) asm volatile("cp.async.wait_group 1;");
        else              asm volatile("cp.async.wait_group 0;");
        __syncthreads();

#pragma unroll
        for (int ks = 0; ks < 2; ++ks) {
            const int j0 = ks * 8 + kq;
            uint32_t a[4][4];
#pragma unroll
            for (int mt = 0; mt < 4; ++mt) {
                const int rr = r0 + mt * 16;
                a[mt][0] = sm.As[cur][rr][j0];
                a[mt][1] = sm.As[cur][rr + 8][j0];
                a[mt][2] = sm.As[cur][rr][j0 + 4];
                a[mt][3] = sm.As[cur][rr + 8][j0 + 4];
            }
#pragma unroll
            for (int nt = 0; nt < 4; ++nt) {
                uint32_t b[2];
                b[0] = sm.Bs[cur][n0 + nt * 8][j0];
                b[1] = sm.Bs[cur][n0 + nt * 8][j0 + 4];
#pragma unroll
                for (int mt = 0; mt < 4; ++mt)
                    mma_f16(c[mt][nt], a[mt], b);
            }
        }

        if (kb + 2 < NIT) issue((kb + 2) % 3, kb + 2);
    }

    const float scale = (z == 0) ? 0.125f : 1.0f;
#pragma unroll
    for (int mt = 0; mt < 4; ++mt) {
        const int rbase = rowBase + wm * 64 + mt * 16 + ng;
#pragma unroll
        for (int nt = 0; nt < 4; ++nt) {
            const int n = nBase + wn * 32 + nt * 8 + 2 * kq;
            const float2 bi = *(const float2*)&bias[n];
            const int hh = n >> 6, d = n & 63;
#pragma unroll
            for (int half_ = 0; half_ < 2; ++half_) {
                const int m = rbase + half_ * 8;
                const int bidx = m >> 10, t = m & 1023;
                float ox = fmaxf(c[mt][nt][half_ * 2 + 0] + bi.x, 0.f) * scale;
                float oy = fmaxf(c[mt][nt][half_ * 2 + 1] + bi.y, 0.f) * scale;
                if (z < 2) {
                    __half* dst = (z == 0) ? g_qh16 : g_kh16;
                    *(__half2*)&dst[((size_t)(hh * 8 + bidx) * Tt + t) * DH + d] =
                        __floats2half2_rn(ox, oy);
                } else {
                    g_vt16[((size_t)(hh * 8 + bidx) * DH + d) * Tt + t]     = __float2half_rn(ox);
                    g_vt16[((size_t)(hh * 8 + bidx) * DH + d + 1) * Tt + t] = __float2half_rn(oy);
                }
            }
        }
    }
}

// ---------------------------------------------------------------------------
// FP16 flash attention v2:
//  - Q fragments hoisted to registers (loop-invariant)
//  - P never touches smem: PV A-fragments are direct repacks of sc regs
//  - triple-buffered K/V with depth-2 prefetch (wait_group 1)
// ---------------------------------------------------------------------------
struct AttnSmem {
    uint32_t K[3][64][36];   // 27648 B [c][d-pair]
    uint32_t V[3][64][36];   // 27648 B V^T: [d][c-pair]
    uint32_t Q[64][36];      //  9216 B (prologue only after frag hoist)
    float pk[17][68];        //  4624 B (pek in prologue, pev in epilogue)
    float qrel[64][17];
    float wsum[64][16];
};

__global__ __launch_bounds__(128) void attn_kernel(
    const float* __restrict__ pe_k, const float* __restrict__ pe_v)
{
    extern __shared__ __align__(1024) char smem_raw[];
    AttnSmem& s = *reinterpret_cast<AttnSmem*>(smem_raw);

    const int tid  = threadIdx.x;
    const int lane = tid & 31;
    const int w    = tid >> 5;
    const int kq   = lane & 3;
    const int ng   = lane >> 2;
    const int it   = 15 - (int)blockIdx.x;
    const int hb   = blockIdx.y;
    const int hh = hb >> 3, bidx = hb & 7;

    const __half* qbase = g_qh16 + (size_t)hb * Tt * DH;
    const __half* kbase = g_kh16 + (size_t)hb * Tt * DH;
    const __half* vbase = g_vt16 + (size_t)hb * DH * Tt;

    const uint32_t kS = smem_u32(&s.K[0][0][0]);
    const uint32_t vS = smem_u32(&s.V[0][0][0]);
    const uint32_t qS = smem_u32(&s.Q[0][0]);

    auto issue_tile = [&](int buf, int jt) {
#pragma unroll
        for (int ii = 0; ii < 4; ++ii) {
            const int i = tid + ii * 128;
            const int r = i >> 3, c8 = i & 7;
            cp16(kS + (((buf * 64 + r) * 36 + c8 * 4) << 2),
                 &kbase[(size_t)(jt * 64 + r) * DH + c8 * 8]);
        }
#pragma unroll
        for (int ii = 0; ii < 4; ++ii) {
            const int i = tid + ii * 128;
            const int d = i >> 3, c8 = i & 7;
            cp16(vS + (((buf * 64 + d) * 36 + c8 * 4) << 2),
                 &vbase[(size_t)d * Tt + jt * 64 + c8 * 8]);
        }
        asm volatile("cp.async.commit_group;");
    };

    // Prologue: tile0, Q, tile1 (3 groups)
    issue_tile(0, 0);
#pragma unroll
    for (int ii = 0; ii < 4; ++ii) {
        const int i = tid + ii * 128;
        const int r = i >> 3, c8 = i & 7;
        cp16(qS + ((r * 36 + c8 * 4) << 2),
             &qbase[(size_t)(it * 64 + r) * DH + c8 * 8]);
    }
    asm volatile("cp.async.commit_group;");
    if (it >= 1) issue_tile(1, 1);

    for (int i = tid; i < 17 * 16; i += 128) {
        int m = i / 16, dq = i % 16;
        *(float4*)&s.pk[m][dq * 4] = *(const float4*)&pe_k[m * DH + dq * 4];
    }
    for (int i = tid; i < 1024; i += 128)
        (&s.wsum[0][0])[i] = 0.f;

    if (it >= 1) asm volatile("cp.async.wait_group 1;");  // tile0 + Q done
    else         asm volatile("cp.async.wait_group 0;");
    __syncthreads();

    // qrel[r][m] = Qscaled . pe_k[m]
    for (int i = tid; i < 64 * 17; i += 128) {
        int r = i / 17, m = i % 17;
        float acc = 0.f;
#pragma unroll
        for (int j = 0; j < 32; ++j) {
            float2 f = __half22float2(*(const __half2*)&s.Q[r][j]);
            acc = fmaf(f.x, s.pk[m][2 * j], acc);
            acc = fmaf(f.y, s.pk[m][2 * j + 1], acc);
        }
        s.qrel[r][m] = acc;
    }
    __syncthreads();

    const int rl0 = w * 16 + ng;
    const float qrel0_0 = s.qrel[rl0][0];
    const float qrel0_1 = s.qrel[rl0 + 8][0];

    // Hoist Q fragments (loop-invariant)
    uint32_t qa[4][4];
#pragma unroll
    for (int ks = 0; ks < 4; ++ks) {
        const int j0 = ks * 8 + kq;
        qa[ks][0] = s.Q[rl0][j0];
        qa[ks][1] = s.Q[rl0 + 8][j0];
        qa[ks][2] = s.Q[rl0][j0 + 4];
        qa[ks][3] = s.Q[rl0 + 8][j0 + 4];
    }

    float o[8][4] = {};
    float mrow[2] = {-1e30f, -1e30f};
    float lrow[2] = {};

    for (int jt = 0; jt <= it; ++jt) {
        const int cur = jt % 3;
        if (jt < it) asm volatile("cp.async.wait_group 1;");
        else         asm volatile("cp.async.wait_group 0;");
        __syncthreads();
        // prefetch jt+2 into buffer (jt+2)%3 (last read at iter jt-1)
        if (jt + 2 <= it) issue_tile((jt + 2) % 3, jt + 2);

        // ---- S = Qs @ K^T ----
        float sc[8][4] = {};
#pragma unroll
        for (int ks = 0; ks < 4; ++ks) {
            const int j0 = ks * 8 + kq;
#pragma unroll
            for (int nt = 0; nt < 8; ++nt) {
                uint32_t b[2];
                b[0] = s.K[cur][nt * 8 + ng][j0];
                b[1] = s.K[cur][nt * 8 + ng][j0 + 4];
                mma_f16(sc[nt], qa[ks], b);
            }
        }

        const bool near = (jt >= it - 1);
        if (near) {
#pragma unroll
            for (int nt = 0; nt < 8; ++nt) {
#pragma unroll
                for (int ci = 0; ci < 4; ++ci) {
                    const int row_l = rl0 + ((ci >> 1) << 3);
                    const int tg = it * 64 + row_l;
                    const int sg = jt * 64 + nt * 8 + 2 * kq + (ci & 1);
                    const int delta = sg - tg;
                    if (delta > 0) sc[nt][ci] = -1e30f;
                    else {
                        int mi = delta + 16; if (mi < 0) mi = 0;
                        sc[nt][ci] += s.qrel[row_l][mi];
                    }
                }
            }
        } else {
#pragma unroll
            for (int nt = 0; nt < 8; ++nt) {
                sc[nt][0] += qrel0_0;
                sc[nt][1] += qrel0_0;
                sc[nt][2] += qrel0_1;
                sc[nt][3] += qrel0_1;
            }
        }

        // ---- online softmax ----
        float mt0 = -1e30f, mt1 = -1e30f;
#pragma unroll
        for (int nt = 0; nt < 8; ++nt) {
            mt0 = fmaxf(mt0, fmaxf(sc[nt][0], sc[nt][1]));
            mt1 = fmaxf(mt1, fmaxf(sc[nt][2], sc[nt][3]));
        }
        mt0 = fmaxf(mt0, __shfl_xor_sync(0xffffffffu, mt0, 1));
        mt0 = fmaxf(mt0, __shfl_xor_sync(0xffffffffu, mt0, 2));
        mt1 = fmaxf(mt1, __shfl_xor_sync(0xffffffffu, mt1, 1));
        mt1 = fmaxf(mt1, __shfl_xor_sync(0xffffffffu, mt1, 2));

        const float mnew0 = fmaxf(mrow[0], mt0);
        const float mnew1 = fmaxf(mrow[1], mt1);
        const float alpha0 = __expf(mrow[0] - mnew0);
        const float alpha1 = __expf(mrow[1] - mnew1);
        mrow[0] = mnew0; mrow[1] = mnew1;

#pragma unroll
        for (int nt = 0; nt < 8; ++nt) {
            sc[nt][0] = __expf(sc[nt][0] - mnew0);
            sc[nt][1] = __expf(sc[nt][1] - mnew0);
            sc[nt][2] = __expf(sc[nt][2] - mnew1);
            sc[nt][3] = __expf(sc[nt][3] - mnew1);
        }

        // ---- P fragments direct in registers (no smem) ----
        uint32_t pa[4][4];
#pragma unroll
        for (int j = 0; j < 4; ++j) {
            pa[j][0] = packh2(sc[2 * j][0],     sc[2 * j][1]);
            pa[j][1] = packh2(sc[2 * j][2],     sc[2 * j][3]);
            pa[j][2] = packh2(sc[2 * j + 1][0], sc[2 * j + 1][1]);
            pa[j][3] = packh2(sc[2 * j + 1][2], sc[2 * j + 1][3]);
        }

        float ps0 = 0.f, ps1 = 0.f;
#pragma unroll
        for (int nt = 0; nt < 8; ++nt) {
            ps0 += sc[nt][0] + sc[nt][1];
            ps1 += sc[nt][2] + sc[nt][3];
        }
        ps0 += __shfl_xor_sync(0xffffffffu, ps0, 1);
        ps0 += __shfl_xor_sync(0xffffffffu, ps0, 2);
        ps1 += __shfl_xor_sync(0xffffffffu, ps1, 1);
        ps1 += __shfl_xor_sync(0xffffffffu, ps1, 2);
        lrow[0] = lrow[0] * alpha0 + ps0;
        lrow[1] = lrow[1] * alpha1 + ps1;

#pragma unroll
        for (int nt = 0; nt < 8; ++nt) {
            o[nt][0] *= alpha0; o[nt][1] *= alpha0;
            o[nt][2] *= alpha1; o[nt][3] *= alpha1;
        }

        // ---- wsum bookkeeping ----
#pragma unroll
        for (int j = 0; j < 4; ++j) {
            s.wsum[rl0][kq * 4 + j]     *= alpha0;
            s.wsum[rl0 + 8][kq * 4 + j] *= alpha1;
        }
        __syncwarp();
        if (near) {
#pragma unroll
            for (int nt = 0; nt < 8; ++nt) {
#pragma unroll
                for (int ci = 0; ci < 4; ++ci) {
                    const int row_l = rl0 + ((ci >> 1) << 3);
                    const int delta = (jt * 64 + nt * 8 + 2 * kq + (ci & 1)) - (it * 64 + row_l);
                    if (delta >= -15 && delta <= 0)
                        s.wsum[row_l][delta + 15] += sc[nt][ci];
                }
            }
        }
        __syncwarp();

        // ---- O += P @ V ----
#pragma unroll
        for (int ks = 0; ks < 4; ++ks) {
            const int j0 = ks * 8 + kq;
#pragma unroll
            for (int nt = 0; nt < 8; ++nt) {
                uint32_t b[2];
                b[0] = s.V[cur][nt * 8 + ng][j0];
                b[1] = s.V[cur][nt * 8 + ng][j0 + 4];
                mma_f16(o[nt], pa[ks], b);
            }
        }
    }

    __syncthreads();
    for (int i = tid; i < 17 * 16; i += 128) {
        int m = i / 16, dq = i % 16;
        *(float4*)&s.pk[m][dq * 4] = *(const float4*)&pe_v[m * DH + dq * 4];
    }
    __syncthreads();

#pragma unroll
    for (int half_ = 0; half_ < 2; ++half_) {
        const int rl = rl0 + 8 * half_;
        const int tg = it * 64 + rl;
        const float l = lrow[half_];
        float wm[16], sumw = 0.f;
#pragma unroll
        for (int m = 0; m < 16; ++m) { wm[m] = s.wsum[rl][m]; sumw += wm[m]; }
        const float w0 = l - sumw;
        const float inv = 1.f / l;
#pragma unroll
        for (int nt = 0; nt < 8; ++nt) {
            const int d0 = nt * 8 + 2 * kq;
            float acc0 = o[nt][half_ * 2 + 0] + w0 * s.pk[0][d0];
            float acc1 = o[nt][half_ * 2 + 1] + w0 * s.pk[0][d0 + 1];
#pragma unroll
            for (int m = 1; m <= 16; ++m) {
                acc0 = fmaf(wm[m - 1], s.pk[m][d0], acc0);
                acc1 = fmaf(wm[m - 1], s.pk[m][d0 + 1], acc1);
            }
            *(__half2*)&g_att16[((size_t)(bidx * Tt) + tg) * Uu + hh * DH + d0] =
                __floats2half2_rn(acc0 * inv, acc1 * inv);
        }
    }
}

// ---------------------------------------------------------------------------
// Fused out-projection + residual + LayerNorm (r13 winner, unchanged).
// ---------------------------------------------------------------------------
struct OProjSmem {
    uint32_t As[4][64][12];     // 12288 B [r][k-pair]
    uint32_t Bs[4][512][12];    // 98304 B [n][k-pair]
    float part[2][8][64];       // 4096 B
    float mu[64];
    float rs[64];
};

__global__ __launch_bounds__(256) void oproj_ln(
    const float* __restrict__ bo,
    const float* __restrict__ res,
    const float* __restrict__ gamma, const float* __restrict__ beta,
    float* __restrict__ out)
{
    extern __shared__ __align__(1024) char smem_raw[];
    OProjSmem& sm = *reinterpret_cast<OProjSmem*>(smem_raw);

    const int tid  = threadIdx.x;
    const int lane = tid & 31;
    const int w    = tid >> 5;
    const int kq   = lane & 3;
    const int ng   = lane >> 2;
    const int rowBase = blockIdx.x * 64;

    const __half* Wt = g_wt16[3];
    const uint32_t aS = smem_u32(&sm.As[0][0][0]);
    const uint32_t bS = smem_u32(&sm.Bs[0][0][0]);

    auto issue = [&](int s, int kt) {
        const int kb = kt * 16;
        if (tid < 128) {
            const int r = tid >> 1, c2 = tid & 1;
            cp16(aS + (((s * 64 + r) * 12 + c2 * 4) << 2),
                 &g_att16[(size_t)(rowBase + r) * Uu + kb + c2 * 8]);
        }
#pragma unroll
        for (int ii = 0; ii < 4; ++ii) {
            const int idx = tid + ii * 256;
            const int n = idx >> 1, c2 = idx & 1;
            cp16(bS + (((s * 512 + n) * 12 + c2 * 4) << 2),
                 &Wt[(size_t)n * Uu + kb + c2 * 8]);
        }
        asm volatile("cp.async.commit_group;");
    };

    constexpr int NIT = Uu / 16;   // 32
    issue(0, 0);
    issue(1, 1);
    issue(2, 2);

    float c[4][8][4] = {};

    for (int kb = 0; kb < NIT; ++kb) {
        const int cur = kb & 3;
        if      (kb + 2 < NIT) asm volatile("cp.async.wait_group 2;");
        else if (kb + 1 < NIT) asm volatile("cp.async.wait_group 1;");
        else                   asm volatile("cp.async.wait_group 0;");
        __syncthreads();

        uint32_t a[4][4];
#pragma unroll
        for (int mt = 0; mt < 4; ++mt) {
            const int r0 = mt * 16 + ng;
            a[mt][0] = sm.As[cur][r0][kq];
            a[mt][1] = sm.As[cur][r0 + 8][kq];
            a[mt][2] = sm.As[cur][r0][kq + 4];
            a[mt][3] = sm.As[cur][r0 + 8][kq + 4];
        }
#pragma unroll
        for (int nt = 0; nt < 8; ++nt) {
            uint32_t b[2];
            const int n0 = w * 64 + nt * 8 + ng;
            b[0] = sm.Bs[cur][n0][kq];
            b[1] = sm.Bs[cur][n0][kq + 4];
#pragma unroll
            for (int mt = 0; mt < 4; ++mt)
                mma_f16(c[mt][nt], a[mt], b);
        }

        if (kb + 3 < NIT) issue((kb + 3) & 3, kb + 3);
    }

    float psum[8] = {}, psq[8] = {};
#pragma unroll
    for (int mt = 0; mt < 4; ++mt) {
#pragma unroll
        for (int half_ = 0; half_ < 2; ++half_) {
            const int m = rowBase + mt * 16 + ng + half_ * 8;
            const int slot = mt * 2 + half_;
#pragma unroll
            for (int nt = 0; nt < 8; ++nt) {
                const int n = w * 64 + nt * 8 + 2 * kq;
                const float2 bi = *(const float2*)&bo[n];
                const float2 r2 = *(const float2*)&res[(size_t)m * Uu + n];
                float vx = fmaxf(c[mt][nt][half_ * 2 + 0] + bi.x, 0.f) + r2.x;
                float vy = fmaxf(c[mt][nt][half_ * 2 + 1] + bi.y, 0.f) + r2.y;
                c[mt][nt][half_ * 2 + 0] = vx;
                c[mt][nt][half_ * 2 + 1] = vy;
                psum[slot] += vx + vy;
                psq[slot]  += vx * vx + vy * vy;
            }
        }
    }
#pragma unroll
    for (int slot = 0; slot < 8; ++slot) {
        psum[slot] += __shfl_xor_sync(0xffffffffu, psum[slot], 1);
        psum[slot] += __shfl_xor_sync(0xffffffffu, psum[slot], 2);
        psq[slot]  += __shfl_xor_sync(0xffffffffu, psq[slot], 1);
        psq[slot]  += __shfl_xor_sync(0xffffffffu, psq[slot], 2);
    }
    if (kq == 0) {
#pragma unroll
        for (int mt = 0; mt < 4; ++mt)
#pragma unroll
            for (int half_ = 0; half_ < 2; ++half_) {
                const int rl = mt * 16 + ng + half_ * 8;
                sm.part[0][w][rl] = psum[mt * 2 + half_];
                sm.part[1][w][rl] = psq[mt * 2 + half_];
            }
    }
    __syncthreads();

    if (tid < 64) {
        float su = 0.f, sq = 0.f;
#pragma unroll
        for (int wi = 0; wi < 8; ++wi) {
            su += sm.part[0][wi][tid];
            sq += sm.part[1][wi][tid];
        }
        const float mu = su * (1.f / Uu);
        const float var = sq * (1.f / Uu) - mu * mu;
        sm.mu[tid] = mu;
        sm.rs[tid] = rsqrtf(var + 1e-3f);
    }
    __syncthreads();

#pragma unroll
    for (int mt = 0; mt < 4; ++mt) {
#pragma unroll
        for (int half_ = 0; half_ < 2; ++half_) {
            const int rl = mt * 16 + ng + half_ * 8;
            const int m = rowBase + rl;
            const float mu = sm.mu[rl];
            const float rstd = sm.rs[rl];
#pragma unroll
            for (int nt = 0; nt < 8; ++nt) {
                const int n = w * 64 + nt * 8 + 2 * kq;
                const float2 g2 = *(const float2*)&gamma[n];
                const float2 b2 = *(const float2*)&beta[n];
                float2 o;
                o.x = (c[mt][nt][half_ * 2 + 0] - mu) * rstd * g2.x + b2.x;
                o.y = (c[mt][nt][half_ * 2 + 1] - mu) * rstd * g2.y + b2.y;
                *(float2*)&out[(size_t)m * Uu + n] = o;
            }
        }
    }
}

// ---------------------------------------------------------------------------
extern "C" void kernel_launch(void* const* d_in, const int* in_sizes, int n_in,
                              void* d_out, int out_size) {
    (void)n_in; (void)out_size;

    int iq, ik, iv, iWq, ibq, iWk, ibk, iWv, ibv, iWo, ibo, ig, ibe, ipk, ipv;
    if (in_sizes[0] == Bb * Tt * Uu) {
        iq = 0; ik = 1; iv = 2; iWq = 3; ibq = 4; iWk = 5; ibk = 6;
        iWv = 7; ibv = 8; iWo = 9; ibo = 10; ig = 11; ibe = 12; ipk = 13; ipv = 14;
    } else if (in_sizes[0] == Uu * Uu) {
        iWk = 0; iWo = 1; iWq = 2; iWv = 3; ibe = 4; ibk = 5; ibo = 6;
        ibq = 7; ibv = 8; ig = 9; ik = 10; ipk = 11; ipv = 12; iq = 13; iv = 14;
    } else {
        ibe = 0; ibk = 1; ibo = 2; ibq = 3; ibv = 4; ig = 5; ik = 6;
        ipk = 7; ipv = 8; iq = 9; iv = 10; iWk = 11; iWo = 12; iWq = 13; iWv = 14;
    }

    const float* q    = (const float*)d_in[iq];
    const float* k    = (const float*)d_in[ik];
    const float* v    = (const float*)d_in[iv];
    const float* Wq   = (const float*)d_in[iWq];
    const float* bq   = (const float*)d_in[ibq];
    const float* Wk   = (const float*)d_in[iWk];
    const float* bk   = (const float*)d_in[ibk];
    const float* Wv   = (const float*)d_in[iWv];
    const float* bv   = (const float*)d_in[ibv];
    const float* Wo   = (const float*)d_in[iWo];
    const float* bo   = (const float*)d_in[ibo];
    const float* gamma= (const float*)d_in[ig];
    const float* beta = (const float*)d_in[ibe];
    const float* pek  = (const float*)d_in[ipk];
    const float* pev  = (const float*)d_in[ipv];
    float* out = (float*)d_out;

    cudaFuncSetAttribute(attn_kernel, cudaFuncAttributeMaxDynamicSharedMemorySize,
                         (int)sizeof(AttnSmem));
    cudaFuncSetAttribute(proj_gemm, cudaFuncAttributeMaxDynamicSharedMemorySize,
                         (int)sizeof(ProjSmem));
    cudaFuncSetAttribute(oproj_ln, cudaFuncAttributeMaxDynamicSharedMemorySize,
                         (int)sizeof(OProjSmem));

    // Convert inputs + weights to fp16 (weights transposed)
    cvt_in<<<dim3(MR * Uu / 4 / 512, 3), 512>>>(q, k, v);
    cvt_w<<<dim3(16, 16, 4), 256>>>(Wq, Wk, Wv, Wo);

    // Q/K/V projections (fp16 mma), head-split fp16 outputs
    proj_gemm<<<dim3(4, 64, 3), 256, sizeof(ProjSmem)>>>(bq, bk, bv);

    attn_kernel<<<dim3(16, 64), 128, sizeof(AttnSmem)>>>(pek, pev);

    // Fused output projection + residual + LayerNorm -> final fp32 output
    oproj_ln<<<128, 256, sizeof(OProjSmem)>>>(bo, q, gamma, beta, out);
}